// round 4
// baseline (speedup 1.0000x reference)
#include <cuda_runtime.h>

#define NAB 20000
#define NAG 20000
#define NTOT 40000
#define FDIM 256
#define EAB 320000
#define EAG 320000
#define ED 640000
#define EPSV 1e-5f

// ---------------- scratch (device globals; no allocs) ----------------
__device__ float g_h[NTOT * FDIM];    // 0: [h_ab ; h_ag], kept for final heads
__device__ float g_xa[NTOT * FDIM];   // 1: GAT1 output
__device__ float g_xb[NTOT * FDIM];   // 2: GAT2 output
__device__ float g_tmp[NTOT * FDIM];  // 3: h = x @ W scratch
__device__ float g_deg[NTOT];
__device__ float g_es[NTOT];
__device__ float g_ed[NTOT];
__device__ float g_eself[NTOT];
__device__ float g_m[NTOT];
__device__ float g_s[NTOT];
__device__ unsigned g_menc[NTOT];
__device__ float g_csum[4][FDIM];
__device__ float g_csq[4][FDIM];

__device__ __forceinline__ float* BUF(int which) {
    switch (which) {
        case 0: return g_h;
        case 1: return g_xa;
        case 2: return g_xb;
        default: return g_tmp;
    }
}

// order-preserving float<->uint encoding for atomicMax
__device__ __forceinline__ unsigned fenc(float x) {
    unsigned u = __float_as_uint(x);
    return (u & 0x80000000u) ? ~u : (u | 0x80000000u);
}
__device__ __forceinline__ float fdec(unsigned e) {
    return __uint_as_float((e & 0x80000000u) ? (e & 0x7FFFFFFFu) : ~e);
}
__device__ __forceinline__ float lrelu(float x) { return x > 0.f ? x : 0.2f * x; }

// ---------------- GEMM: g_tmp[M,256] = A[M,256] @ B[256,256] ----------------
// awhich < 0 -> A = Aext (harness input); else A = BUF(awhich)
__global__ void k_gemm(const float* __restrict__ Aext, int awhich,
                       const float* __restrict__ B, int M) {
    const float* A = (awhich < 0) ? Aext : BUF(awhich);
    __shared__ float As[64][16];
    __shared__ float Bs[16][64];
    int t = threadIdx.x;  // 256 threads
    int bx = blockIdx.x;  // N tile (4)
    int by = blockIdx.y;  // M tile
    int tx = t & 15, ty = t >> 4;
    int arow = t >> 2;
    int acol = (t & 3) << 2;
    int brow = t >> 4;
    int bcol = (t & 15) << 2;
    int gar = by * 64 + arow;
    float acc[4][4];
#pragma unroll
    for (int i = 0; i < 4; i++)
#pragma unroll
        for (int j = 0; j < 4; j++) acc[i][j] = 0.f;

    for (int k0 = 0; k0 < 256; k0 += 16) {
        float4 av = make_float4(0.f, 0.f, 0.f, 0.f);
        if (gar < M) av = *(const float4*)(A + gar * 256 + k0 + acol);
        *(float4*)&As[arow][acol] = av;
        *(float4*)&Bs[brow][bcol] = *(const float4*)(B + (k0 + brow) * 256 + bx * 64 + bcol);
        __syncthreads();
#pragma unroll
        for (int k = 0; k < 16; k++) {
            float a0 = As[ty * 4 + 0][k], a1 = As[ty * 4 + 1][k];
            float a2 = As[ty * 4 + 2][k], a3 = As[ty * 4 + 3][k];
            float b0 = Bs[k][tx * 4 + 0], b1 = Bs[k][tx * 4 + 1];
            float b2 = Bs[k][tx * 4 + 2], b3 = Bs[k][tx * 4 + 3];
            acc[0][0] += a0 * b0; acc[0][1] += a0 * b1; acc[0][2] += a0 * b2; acc[0][3] += a0 * b3;
            acc[1][0] += a1 * b0; acc[1][1] += a1 * b1; acc[1][2] += a1 * b2; acc[1][3] += a1 * b3;
            acc[2][0] += a2 * b0; acc[2][1] += a2 * b1; acc[2][2] += a2 * b2; acc[2][3] += a2 * b3;
            acc[3][0] += a3 * b0; acc[3][1] += a3 * b1; acc[3][2] += a3 * b2; acc[3][3] += a3 * b3;
        }
        __syncthreads();
    }
#pragma unroll
    for (int i = 0; i < 4; i++) {
        int row = by * 64 + ty * 4 + i;
        if (row < M)
            *(float4*)(g_tmp + row * 256 + bx * 64 + tx * 4) =
                make_float4(acc[i][0], acc[i][1], acc[i][2], acc[i][3]);
    }
}

// ---------------- GCN ----------------
__global__ void k_deg_init(int n) {
    int i = blockIdx.x * blockDim.x + threadIdx.x;
    if (i < n) g_deg[i] = 1.0f;  // self loop
}
__global__ void k_deg_acc(const int* __restrict__ dst, int ne) {
    int e = blockIdx.x * blockDim.x + threadIdx.x;
    if (e < ne) atomicAdd(&g_deg[dst[e]], 1.0f);
}
__global__ void k_dinv(int n) {
    int i = blockIdx.x * blockDim.x + threadIdx.x;
    if (i < n) g_deg[i] = rsqrtf(fmaxf(g_deg[i], 1.0f));
}
// out = g_tmp * dinv^2 (self loop) + bias
__global__ void k_gcn_init(const float* __restrict__ b, int outoff, int n) {
    int idx = blockIdx.x * blockDim.x + threadIdx.x;
    if (idx < n * FDIM) {
        int i = idx >> 8;
        int f = idx & 255;
        float d = g_deg[i];
        g_h[outoff + idx] = g_tmp[idx] * d * d + b[f];
    }
}
__global__ void k_gcn_scatter(const int* __restrict__ src, const int* __restrict__ dst,
                              int outoff, int ne) {
    int w = (blockIdx.x * blockDim.x + threadIdx.x) >> 5;
    int lane = threadIdx.x & 31;
    if (w >= ne) return;
    int s = src[w], d = dst[w];
    float norm = g_deg[s] * g_deg[d];
    const float4* hp = (const float4*)(g_tmp + s * FDIM);
    float* op = g_h + outoff + d * FDIM;
#pragma unroll
    for (int c = 0; c < 2; c++) {
        float4 v = hp[lane + c * 32];
        int base = (lane + c * 32) * 4;
        atomicAdd(op + base + 0, v.x * norm);
        atomicAdd(op + base + 1, v.y * norm);
        atomicAdd(op + base + 2, v.z * norm);
        atomicAdd(op + base + 3, v.w * norm);
    }
}

// ---------------- BN ----------------
__global__ void k_zero_stats() {
    g_csum[blockIdx.x][threadIdx.x] = 0.f;
    g_csq[blockIdx.x][threadIdx.x] = 0.f;
}
__global__ void k_colstats(int which, int off, int nrows, int slot) {
    const float* x = BUF(which) + off;
    int col = threadIdx.x;
    float s = 0.f, q = 0.f;
    for (int r = blockIdx.x; r < nrows; r += gridDim.x) {
        float v = x[r * FDIM + col];
        s += v;
        q += v * v;
    }
    atomicAdd(&g_csum[slot][col], s);
    atomicAdd(&g_csq[slot][col], q);
}
__global__ void k_bn_relu(int which, int off, int nrows, int slot,
                          const float* __restrict__ g, const float* __restrict__ be) {
    float* x = BUF(which) + off;
    int idx = blockIdx.x * blockDim.x + threadIdx.x;
    if (idx < nrows * FDIM) {
        int f = idx & 255;
        float n = (float)nrows;
        float mu = g_csum[slot][f] / n;
        float var = g_csq[slot][f] / n - mu * mu;
        float v = (x[idx] - mu) * rsqrtf(var + EPSV) * g[f] + be[f];
        x[idx] = v > 0.f ? v : 0.f;
    }
}

// ---------------- GAT ----------------
// per-node dot products + self-loop logit + max init, one warp per node
__global__ void k_dots(const float* __restrict__ a_s, const float* __restrict__ a_d) {
    int w = (blockIdx.x * blockDim.x + threadIdx.x) >> 5;
    int lane = threadIdx.x & 31;
    if (w >= NTOT) return;
    const float4* hp = (const float4*)(g_tmp + w * FDIM);
    const float4* ap = (const float4*)a_s;
    const float4* dp = (const float4*)a_d;
    float s = 0.f, d = 0.f;
#pragma unroll
    for (int c = 0; c < 2; c++) {
        float4 hv = hp[lane + c * 32];
        float4 av = ap[lane + c * 32];
        float4 dv = dp[lane + c * 32];
        s += hv.x * av.x + hv.y * av.y + hv.z * av.z + hv.w * av.w;
        d += hv.x * dv.x + hv.y * dv.y + hv.z * dv.z + hv.w * dv.w;
    }
#pragma unroll
    for (int o = 16; o; o >>= 1) {
        s += __shfl_xor_sync(0xFFFFFFFFu, s, o);
        d += __shfl_xor_sync(0xFFFFFFFFu, d, o);
    }
    if (lane == 0) {
        g_es[w] = s;
        g_ed[w] = d;
        float e = lrelu(s + d);  // self-loop logit
        g_eself[w] = e;
        g_menc[w] = fenc(e);
    }
}
__global__ void k_edge_max(const int* __restrict__ src, const int* __restrict__ dst, int ne) {
    int e = blockIdx.x * blockDim.x + threadIdx.x;
    if (e < ne) {
        int d = dst[e];
        float v = lrelu(g_es[src[e]] + g_ed[d]);
        atomicMax(&g_menc[d], fenc(v));
    }
}
// accum = g_tmp * exp(e_self - m); s = exp(e_self - m)
__global__ void k_gat_node_init(int accwhich) {
    float* accum = BUF(accwhich);
    int idx = blockIdx.x * blockDim.x + threadIdx.x;
    if (idx < NTOT * FDIM) {
        int i = idx >> 8;
        float m = fdec(g_menc[i]);
        float ex = expf(g_eself[i] - m);
        if ((idx & 255) == 0) {
            g_m[i] = m;
            g_s[i] = ex;
        }
        accum[idx] = g_tmp[idx] * ex;
    }
}
__global__ void k_gat_scatter(const int* __restrict__ src, const int* __restrict__ dst,
                              int accwhich, int ne) {
    float* accum = BUF(accwhich);
    int w = (blockIdx.x * blockDim.x + threadIdx.x) >> 5;
    int lane = threadIdx.x & 31;
    if (w >= ne) return;
    int s = src[w], d = dst[w];
    float e = lrelu(g_es[s] + g_ed[d]);
    float ex = expf(e - g_m[d]);
    if (lane == 0) atomicAdd(&g_s[d], ex);
    const float4* hp = (const float4*)(g_tmp + s * FDIM);
    float* op = accum + d * FDIM;
#pragma unroll
    for (int c = 0; c < 2; c++) {
        float4 v = hp[lane + c * 32];
        int base = (lane + c * 32) * 4;
        atomicAdd(op + base + 0, v.x * ex);
        atomicAdd(op + base + 1, v.y * ex);
        atomicAdd(op + base + 2, v.z * ex);
        atomicAdd(op + base + 3, v.w * ex);
    }
}
__global__ void k_gat_epilogue(int accwhich, const float* __restrict__ b, int dorelu) {
    float* x = BUF(accwhich);
    int idx = blockIdx.x * blockDim.x + threadIdx.x;
    if (idx < NTOT * FDIM) {
        int i = idx >> 8;
        int f = idx & 255;
        float v = x[idx] / g_s[i] + b[f];
        if (dorelu) v = v > 0.f ? v : 0.f;
        x[idx] = v;
    }
}

// ---------------- final heads: relu(bn(cat[x,h])) @ W + b ----------------
__global__ void k_head(int xoff, int hoff, int slot_x, int slot_h,
                       const float* __restrict__ g, const float* __restrict__ be,
                       const float* __restrict__ W, const float* __restrict__ b,
                       float* __restrict__ out, int nrows) {
    __shared__ float red[256];
    const float* xpart = g_xb + xoff;
    const float* hpart = g_h + hoff;
    int row = blockIdx.x;
    int t = threadIdx.x;
    float n = (float)nrows;
    float mu1 = g_csum[slot_x][t] / n;
    float var1 = g_csq[slot_x][t] / n - mu1 * mu1;
    float v1 = (xpart[row * FDIM + t] - mu1) * rsqrtf(var1 + EPSV) * g[t] + be[t];
    v1 = v1 > 0.f ? v1 : 0.f;
    float mu2 = g_csum[slot_h][t] / n;
    float var2 = g_csq[slot_h][t] / n - mu2 * mu2;
    float v2 = (hpart[row * FDIM + t] - mu2) * rsqrtf(var2 + EPSV) * g[FDIM + t] + be[FDIM + t];
    v2 = v2 > 0.f ? v2 : 0.f;
    red[t] = v1 * W[t] + v2 * W[FDIM + t];
    __syncthreads();
#pragma unroll
    for (int o = 128; o; o >>= 1) {
        if (t < o) red[t] += red[t + o];
        __syncthreads();
    }
    if (t == 0) out[row] = red[0] + b[0];
}

// ---------------- host orchestration (launches ONLY) ----------------
static void run_gcn(const float* x, const float* W, const float* b, const int* src,
                    const int* dst, int ne, int n, const float* g, const float* be,
                    int outoff) {
    k_deg_init<<<(n + 255) / 256, 256>>>(n);
    k_deg_acc<<<(ne + 255) / 256, 256>>>(dst, ne);
    k_dinv<<<(n + 255) / 256, 256>>>(n);
    dim3 gg(4, (n + 63) / 64);
    k_gemm<<<gg, 256>>>(x, -1, W, n);
    k_gcn_init<<<(n * FDIM + 255) / 256, 256>>>(b, outoff, n);
    k_gcn_scatter<<<(ne + 7) / 8, 256>>>(src, dst, outoff, ne);
    k_zero_stats<<<1, 256>>>();
    k_colstats<<<256, 256>>>(0, outoff, n, 0);
    k_bn_relu<<<(n * FDIM + 255) / 256, 256>>>(0, outoff, n, 0, g, be);
}

static void run_gat(int inwhich, const float* W, const float* a_s, const float* a_d,
                    const float* b, const int* src, const int* dst, int ne,
                    int accwhich, int dorelu) {
    dim3 gg(4, (NTOT + 63) / 64);
    k_gemm<<<gg, 256>>>(nullptr, inwhich, W, NTOT);
    k_dots<<<(NTOT + 7) / 8, 256>>>(a_s, a_d);
    k_edge_max<<<(ne + 255) / 256, 256>>>(src, dst, ne);
    k_gat_node_init<<<(NTOT * FDIM + 255) / 256, 256>>>(accwhich);
    k_gat_scatter<<<(ne + 7) / 8, 256>>>(src, dst, accwhich, ne);
    k_gat_epilogue<<<(NTOT * FDIM + 255) / 256, 256>>>(accwhich, b, dorelu);
}

extern "C" void kernel_launch(void* const* d_in, const int* in_sizes, int n_in, void* d_out,
                              int out_size) {
    const float* x_ab = (const float*)d_in[0];
    const float* x_ag = (const float*)d_in[1];
    const float* W_gcn = (const float*)d_in[2];
    const float* b_gcn = (const float*)d_in[3];
    const float* g1 = (const float*)d_in[4];
    const float* be1 = (const float*)d_in[5];
    const float* W_aggcn = (const float*)d_in[6];
    const float* b_aggcn = (const float*)d_in[7];
    const float* ag_g1 = (const float*)d_in[8];
    const float* ag_be1 = (const float*)d_in[9];
    const float* W_gat = (const float*)d_in[10];
    const float* a_src = (const float*)d_in[11];
    const float* a_dst = (const float*)d_in[12];
    const float* b_gat = (const float*)d_in[13];
    const float* W_gat2 = (const float*)d_in[14];
    const float* a_src2 = (const float*)d_in[15];
    const float* a_dst2 = (const float*)d_in[16];
    const float* b_gat2 = (const float*)d_in[17];
    const float* ag_g2 = (const float*)d_in[18];
    const float* ag_be2 = (const float*)d_in[19];
    const float* W_agfc = (const float*)d_in[20];
    const float* b_agfc = (const float*)d_in[21];
    const float* g2 = (const float*)d_in[22];
    const float* be2 = (const float*)d_in[23];
    const float* W_fc = (const float*)d_in[24];
    const float* b_fc = (const float*)d_in[25];
    const int* e_ab = (const int*)d_in[26];
    const int* e_ag = (const int*)d_in[27];
    const int* e_d = (const int*)d_in[28];
    float* out = (float*)d_out;

    // GCN on AB graph -> g_h rows [0, NAB)
    run_gcn(x_ab, W_gcn, b_gcn, e_ab, e_ab + EAB, EAB, NAB, g1, be1, 0);
    // GCN on AG graph -> g_h rows [NAB, NTOT)
    run_gcn(x_ag, W_aggcn, b_aggcn, e_ag, e_ag + EAG, EAG, NAG, ag_g1, ag_be1, NAB * FDIM);

    // GAT layer 1: g_h(0) -> g_xa(1), relu
    run_gat(0, W_gat, a_src, a_dst, b_gat, e_d, e_d + ED, ED, 1, 1);
    // GAT layer 2: g_xa(1) -> g_xb(2), no relu
    run_gat(1, W_gat2, a_src2, a_dst2, b_gat2, e_d, e_d + ED, ED, 2, 0);

    // head stats: x1, x2, h_ab, h_ag
    k_zero_stats<<<4, 256>>>();
    k_colstats<<<256, 256>>>(2, 0, NAB, 0);
    k_colstats<<<256, 256>>>(2, NAB * FDIM, NAG, 1);
    k_colstats<<<256, 256>>>(0, 0, NAB, 2);
    k_colstats<<<256, 256>>>(0, NAB * FDIM, NAG, 3);

    // out_ab then out_ag
    k_head<<<NAB, 256>>>(0, 0, 0, 2, g2, be2, W_fc, b_fc, out, NAB);
    k_head<<<NAG, 256>>>(NAB * FDIM, NAB * FDIM, 1, 3, ag_g2, ag_be2, W_agfc, b_agfc,
                         out + NAB, NAG);
}

// round 6
// speedup vs baseline: 1.0375x; 1.0375x over previous
#include <cuda_runtime.h>

#define NAB 20000
#define NAG 20000
#define NTOT 40000
#define FDIM 256
#define EAB 320000
#define EAG 320000
#define ED 640000
#define EPSV 1e-5f

// ---------------- scratch (device globals; no allocs) ----------------
__device__ float g_h[NTOT * FDIM];    // 0: [h_ab ; h_ag], kept for final heads
__device__ float g_xa[NTOT * FDIM];   // 1: GAT1 output
__device__ float g_xb[NTOT * FDIM];   // 2: GAT2 output
__device__ float g_tmp[NTOT * FDIM];  // 3: h = x @ W scratch
__device__ float g_deg[NTOT];
__device__ float g_es[NTOT];
__device__ float g_ed[NTOT];
__device__ float g_eself[NTOT];
__device__ float g_m[NTOT];
__device__ float g_s[NTOT];
__device__ unsigned g_menc[NTOT];
__device__ float g_csum[4][FDIM];
__device__ float g_csq[4][FDIM];

__device__ __forceinline__ float* BUF(int which) {
    switch (which) {
        case 0: return g_h;
        case 1: return g_xa;
        case 2: return g_xb;
        default: return g_tmp;
    }
}

// order-preserving float<->uint encoding for atomicMax
__device__ __forceinline__ unsigned fenc(float x) {
    unsigned u = __float_as_uint(x);
    return (u & 0x80000000u) ? ~u : (u | 0x80000000u);
}
__device__ __forceinline__ float fdec(unsigned e) {
    return __uint_as_float((e & 0x80000000u) ? (e & 0x7FFFFFFFu) : ~e);
}
__device__ __forceinline__ float lrelu(float x) { return x > 0.f ? x : 0.2f * x; }

// ---------------- GEMM: g_tmp[M,256] = A[M,256] @ B[256,256] ----------------
// 128x128 block tile, 8x8 per thread, BK=8. awhich<0 -> A=Aext else BUF(awhich)
__global__ void __launch_bounds__(256, 2)
k_gemm(const float* __restrict__ Aext, int awhich, const float* __restrict__ B, int M) {
    const float* A = (awhich < 0) ? Aext : BUF(awhich);
    __shared__ float As[8][128];  // k-major
    __shared__ float Bs[8][128];
    int t = threadIdx.x;           // 256 threads
    int tx = t & 15, ty = t >> 4;  // 16x16
    int brow0 = blockIdx.y * 128;
    int bcol0 = blockIdx.x * 128;
    // A load: one float4 per thread: row t>>1, cols (t&1)*4
    int arow = t >> 1;
    int acol = (t & 1) << 2;
    // B load: one float4 per thread: krow t>>5, col (t&31)*4
    int bkr = t >> 5;
    int bcl = (t & 31) << 2;
    float acc[8][8];
#pragma unroll
    for (int i = 0; i < 8; i++)
#pragma unroll
        for (int j = 0; j < 8; j++) acc[i][j] = 0.f;

    for (int k0 = 0; k0 < 256; k0 += 8) {
        float4 av = make_float4(0.f, 0.f, 0.f, 0.f);
        int gr = brow0 + arow;
        if (gr < M) av = *(const float4*)(A + gr * 256 + k0 + acol);
        As[acol + 0][arow] = av.x;
        As[acol + 1][arow] = av.y;
        As[acol + 2][arow] = av.z;
        As[acol + 3][arow] = av.w;
        *(float4*)&Bs[bkr][bcl] = *(const float4*)(B + (k0 + bkr) * 256 + bcol0 + bcl);
        __syncthreads();
#pragma unroll
        for (int kk = 0; kk < 8; kk++) {
            float ar[8], br[8];
            *(float4*)(ar + 0) = *(float4*)&As[kk][ty * 8 + 0];
            *(float4*)(ar + 4) = *(float4*)&As[kk][ty * 8 + 4];
            *(float4*)(br + 0) = *(float4*)&Bs[kk][tx * 8 + 0];
            *(float4*)(br + 4) = *(float4*)&Bs[kk][tx * 8 + 4];
#pragma unroll
            for (int i = 0; i < 8; i++)
#pragma unroll
                for (int j = 0; j < 8; j++) acc[i][j] += ar[i] * br[j];
        }
        __syncthreads();
    }
#pragma unroll
    for (int i = 0; i < 8; i++) {
        int row = brow0 + ty * 8 + i;
        if (row < M) {
            *(float4*)(g_tmp + row * 256 + bcol0 + tx * 8 + 0) =
                make_float4(acc[i][0], acc[i][1], acc[i][2], acc[i][3]);
            *(float4*)(g_tmp + row * 256 + bcol0 + tx * 8 + 4) =
                make_float4(acc[i][4], acc[i][5], acc[i][6], acc[i][7]);
        }
    }
}

// ---------------- GCN ----------------
__global__ void k_deg_init(int n) {
    int i = blockIdx.x * blockDim.x + threadIdx.x;
    if (i < n) g_deg[i] = 1.0f;  // self loop
}
__global__ void k_deg_acc(const int* __restrict__ dst, int ne) {
    int e = blockIdx.x * blockDim.x + threadIdx.x;
    if (e < ne) atomicAdd(&g_deg[dst[e]], 1.0f);
}
__global__ void k_dinv(int n) {
    int i = blockIdx.x * blockDim.x + threadIdx.x;
    if (i < n) g_deg[i] = rsqrtf(fmaxf(g_deg[i], 1.0f));
}
// out = g_tmp * dinv^2 (self loop) + bias; float4 per thread
__global__ void k_gcn_init(const float* __restrict__ b, int outoff, int n) {
    int idx = blockIdx.x * blockDim.x + threadIdx.x;  // float4 index
    if (idx < n * 64) {
        int i = idx >> 6;
        int f4 = idx & 63;
        float d = g_deg[i];
        float dd = d * d;
        float4 v = *((const float4*)g_tmp + idx);
        float4 bb = *((const float4*)b + f4);
        v.x = v.x * dd + bb.x;
        v.y = v.y * dd + bb.y;
        v.z = v.z * dd + bb.z;
        v.w = v.w * dd + bb.w;
        *((float4*)(g_h + outoff) + idx) = v;
    }
}
__global__ void k_gcn_scatter(const int* __restrict__ src, const int* __restrict__ dst,
                              int outoff, int ne) {
    int w = (blockIdx.x * blockDim.x + threadIdx.x) >> 5;
    int lane = threadIdx.x & 31;
    if (w >= ne) return;
    int s = src[w], d = dst[w];
    float norm = g_deg[s] * g_deg[d];
    const float4* hp = (const float4*)(g_tmp + s * FDIM);
    float4* op = (float4*)(g_h + outoff + d * FDIM);
#pragma unroll
    for (int c = 0; c < 2; c++) {
        float4 v = hp[lane + c * 32];
        v.x *= norm; v.y *= norm; v.z *= norm; v.w *= norm;
        atomicAdd(op + lane + c * 32, v);
    }
}

// ---------------- BN ----------------
__global__ void k_zero_stats() {
    g_csum[blockIdx.x][threadIdx.x] = 0.f;
    g_csq[blockIdx.x][threadIdx.x] = 0.f;
}
__global__ void k_colstats(int which, int off, int nrows, int slot) {
    const float* x = BUF(which) + off;
    int col = threadIdx.x;
    float s = 0.f, q = 0.f;
    for (int r = blockIdx.x; r < nrows; r += gridDim.x) {
        float v = x[r * FDIM + col];
        s += v;
        q += v * v;
    }
    atomicAdd(&g_csum[slot][col], s);
    atomicAdd(&g_csq[slot][col], q);
}
__global__ void k_bn_relu(int which, int off, int nrows, int slot,
                          const float* __restrict__ g, const float* __restrict__ be) {
    float* x = BUF(which) + off;
    int idx = blockIdx.x * blockDim.x + threadIdx.x;  // float4 index
    if (idx < nrows * 64) {
        int f = (idx & 63) << 2;
        float n = (float)nrows;
        float4 v = *((float4*)x + idx);
        float* pv = &v.x;
#pragma unroll
        for (int j = 0; j < 4; j++) {
            float mu = g_csum[slot][f + j] / n;
            float var = g_csq[slot][f + j] / n - mu * mu;
            float o = (pv[j] - mu) * rsqrtf(var + EPSV) * g[f + j] + be[f + j];
            pv[j] = o > 0.f ? o : 0.f;
        }
        *((float4*)x + idx) = v;
    }
}

// ---------------- GAT ----------------
// per-node dot products + self-loop logit + max init, one warp per node
__global__ void k_dots(const float* __restrict__ a_s, const float* __restrict__ a_d) {
    int w = (blockIdx.x * blockDim.x + threadIdx.x) >> 5;
    int lane = threadIdx.x & 31;
    if (w >= NTOT) return;
    const float4* hp = (const float4*)(g_tmp + w * FDIM);
    const float4* ap = (const float4*)a_s;
    const float4* dp = (const float4*)a_d;
    float s = 0.f, d = 0.f;
#pragma unroll
    for (int c = 0; c < 2; c++) {
        float4 hv = hp[lane + c * 32];
        float4 av = ap[lane + c * 32];
        float4 dv = dp[lane + c * 32];
        s += hv.x * av.x + hv.y * av.y + hv.z * av.z + hv.w * av.w;
        d += hv.x * dv.x + hv.y * dv.y + hv.z * dv.z + hv.w * dv.w;
    }
#pragma unroll
    for (int o = 16; o; o >>= 1) {
        s += __shfl_xor_sync(0xFFFFFFFFu, s, o);
        d += __shfl_xor_sync(0xFFFFFFFFu, d, o);
    }
    if (lane == 0) {
        g_es[w] = s;
        g_ed[w] = d;
        float e = lrelu(s + d);  // self-loop logit
        g_eself[w] = e;
        g_menc[w] = fenc(e);
    }
}
__global__ void k_edge_max(const int* __restrict__ src, const int* __restrict__ dst, int ne) {
    int e = blockIdx.x * blockDim.x + threadIdx.x;
    if (e < ne) {
        int d = dst[e];
        float v = lrelu(g_es[src[e]] + g_ed[d]);
        atomicMax(&g_menc[d], fenc(v));
    }
}
// accum = g_tmp * exp(e_self - m); s = exp(e_self - m); float4 per thread
__global__ void k_gat_node_init(int accwhich) {
    float4* accum = (float4*)BUF(accwhich);
    int idx = blockIdx.x * blockDim.x + threadIdx.x;  // float4 index
    if (idx < NTOT * 64) {
        int i = idx >> 6;
        float m = fdec(g_menc[i]);
        float ex = expf(g_eself[i] - m);
        if ((idx & 63) == 0) {
            g_m[i] = m;
            g_s[i] = ex;
        }
        float4 v = *((const float4*)g_tmp + idx);
        v.x *= ex; v.y *= ex; v.z *= ex; v.w *= ex;
        accum[idx] = v;
    }
}
__global__ void k_gat_scatter(const int* __restrict__ src, const int* __restrict__ dst,
                              int accwhich, int ne) {
    float* accum = BUF(accwhich);
    int w = (blockIdx.x * blockDim.x + threadIdx.x) >> 5;
    int lane = threadIdx.x & 31;
    if (w >= ne) return;
    int s = src[w], d = dst[w];
    float e = lrelu(g_es[s] + g_ed[d]);
    float ex = expf(e - g_m[d]);
    if (lane == 0) atomicAdd(&g_s[d], ex);
    const float4* hp = (const float4*)(g_tmp + s * FDIM);
    float4* op = (float4*)(accum + d * FDIM);
#pragma unroll
    for (int c = 0; c < 2; c++) {
        float4 v = hp[lane + c * 32];
        v.x *= ex; v.y *= ex; v.z *= ex; v.w *= ex;
        atomicAdd(op + lane + c * 32, v);
    }
}
__global__ void k_gat_epilogue(int accwhich, const float* __restrict__ b, int dorelu) {
    float4* x = (float4*)BUF(accwhich);
    int idx = blockIdx.x * blockDim.x + threadIdx.x;  // float4 index
    if (idx < NTOT * 64) {
        int i = idx >> 6;
        int f4 = idx & 63;
        float inv = 1.0f / g_s[i];
        float4 v = x[idx];
        float4 bb = *((const float4*)b + f4);
        v.x = v.x * inv + bb.x;
        v.y = v.y * inv + bb.y;
        v.z = v.z * inv + bb.z;
        v.w = v.w * inv + bb.w;
        if (dorelu) {
            v.x = v.x > 0.f ? v.x : 0.f;
            v.y = v.y > 0.f ? v.y : 0.f;
            v.z = v.z > 0.f ? v.z : 0.f;
            v.w = v.w > 0.f ? v.w : 0.f;
        }
        x[idx] = v;
    }
}

// ---------------- final heads: relu(bn(cat[x,h])) @ W + b ----------------
__global__ void k_head(int xoff, int hoff, int slot_x, int slot_h,
                       const float* __restrict__ g, const float* __restrict__ be,
                       const float* __restrict__ W, const float* __restrict__ b,
                       float* __restrict__ out, int nrows) {
    __shared__ float red[8];
    const float* xpart = g_xb + xoff;
    const float* hpart = g_h + hoff;
    int row = blockIdx.x;
    int t = threadIdx.x;
    int lane = t & 31, wid = t >> 5;
    float n = (float)nrows;
    float mu1 = g_csum[slot_x][t] / n;
    float var1 = g_csq[slot_x][t] / n - mu1 * mu1;
    float v1 = (xpart[row * FDIM + t] - mu1) * rsqrtf(var1 + EPSV) * g[t] + be[t];
    v1 = v1 > 0.f ? v1 : 0.f;
    float mu2 = g_csum[slot_h][t] / n;
    float var2 = g_csq[slot_h][t] / n - mu2 * mu2;
    float v2 = (hpart[row * FDIM + t] - mu2) * rsqrtf(var2 + EPSV) * g[FDIM + t] + be[FDIM + t];
    v2 = v2 > 0.f ? v2 : 0.f;
    float p = v1 * W[t] + v2 * W[FDIM + t];
#pragma unroll
    for (int o = 16; o; o >>= 1) p += __shfl_xor_sync(0xFFFFFFFFu, p, o);
    if (lane == 0) red[wid] = p;
    __syncthreads();
    if (t == 0) {
        float acc = red[0];
#pragma unroll
        for (int i = 1; i < 8; i++) acc += red[i];
        out[row] = acc + b[0];
    }
}

// ---------------- host orchestration (launches ONLY) ----------------
static void run_gcn(const float* x, const float* W, const float* b, const int* src,
                    const int* dst, int ne, int n, const float* g, const float* be,
                    int outoff) {
    k_deg_init<<<(n + 255) / 256, 256>>>(n);
    k_deg_acc<<<(ne + 255) / 256, 256>>>(dst, ne);
    k_dinv<<<(n + 255) / 256, 256>>>(n);
    dim3 gg(2, (n + 127) / 128);
    k_gemm<<<gg, 256>>>(x, -1, W, n);
    k_gcn_init<<<(n * 64 + 255) / 256, 256>>>(b, outoff, n);
    k_gcn_scatter<<<(ne + 7) / 8, 256>>>(src, dst, outoff, ne);
    k_zero_stats<<<1, 256>>>();
    k_colstats<<<256, 256>>>(0, outoff, n, 0);
    k_bn_relu<<<(n * 64 + 255) / 256, 256>>>(0, outoff, n, 0, g, be);
}

static void run_gat(int inwhich, const float* W, const float* a_s, const float* a_d,
                    const float* b, const int* src, const int* dst, int ne,
                    int accwhich, int dorelu) {
    dim3 gg(2, (NTOT + 127) / 128);
    k_gemm<<<gg, 256>>>(nullptr, inwhich, W, NTOT);
    k_dots<<<(NTOT + 7) / 8, 256>>>(a_s, a_d);
    k_edge_max<<<(ne + 255) / 256, 256>>>(src, dst, ne);
    k_gat_node_init<<<(NTOT * 64 + 255) / 256, 256>>>(accwhich);
    k_gat_scatter<<<(ne + 7) / 8, 256>>>(src, dst, accwhich, ne);
    k_gat_epilogue<<<(NTOT * 64 + 255) / 256, 256>>>(accwhich, b, dorelu);
}

extern "C" void kernel_launch(void* const* d_in, const int* in_sizes, int n_in, void* d_out,
                              int out_size) {
    const float* x_ab = (const float*)d_in[0];
    const float* x_ag = (const float*)d_in[1];
    const float* W_gcn = (const float*)d_in[2];
    const float* b_gcn = (const float*)d_in[3];
    const float* g1 = (const float*)d_in[4];
    const float* be1 = (const float*)d_in[5];
    const float* W_aggcn = (const float*)d_in[6];
    const float* b_aggcn = (const float*)d_in[7];
    const float* ag_g1 = (const float*)d_in[8];
    const float* ag_be1 = (const float*)d_in[9];
    const float* W_gat = (const float*)d_in[10];
    const float* a_src = (const float*)d_in[11];
    const float* a_dst = (const float*)d_in[12];
    const float* b_gat = (const float*)d_in[13];
    const float* W_gat2 = (const float*)d_in[14];
    const float* a_src2 = (const float*)d_in[15];
    const float* a_dst2 = (const float*)d_in[16];
    const float* b_gat2 = (const float*)d_in[17];
    const float* ag_g2 = (const float*)d_in[18];
    const float* ag_be2 = (const float*)d_in[19];
    const float* W_agfc = (const float*)d_in[20];
    const float* b_agfc = (const float*)d_in[21];
    const float* g2 = (const float*)d_in[22];
    const float* be2 = (const float*)d_in[23];
    const float* W_fc = (const float*)d_in[24];
    const float* b_fc = (const float*)d_in[25];
    const int* e_ab = (const int*)d_in[26];
    const int* e_ag = (const int*)d_in[27];
    const int* e_d = (const int*)d_in[28];
    float* out = (float*)d_out;

    // GCN on AB graph -> g_h rows [0, NAB)
    run_gcn(x_ab, W_gcn, b_gcn, e_ab, e_ab + EAB, EAB, NAB, g1, be1, 0);
    // GCN on AG graph -> g_h rows [NAB, NTOT)
    run_gcn(x_ag, W_aggcn, b_aggcn, e_ag, e_ag + EAG, EAG, NAG, ag_g1, ag_be1, NAB * FDIM);

    // GAT layer 1: g_h(0) -> g_xa(1), relu
    run_gat(0, W_gat, a_src, a_dst, b_gat, e_d, e_d + ED, ED, 1, 1);
    // GAT layer 2: g_xa(1) -> g_xb(2), no relu
    run_gat(1, W_gat2, a_src2, a_dst2, b_gat2, e_d, e_d + ED, ED, 2, 0);

    // head stats: x1, x2, h_ab, h_ag
    k_zero_stats<<<4, 256>>>();
    k_colstats<<<256, 256>>>(2, 0, NAB, 0);
    k_colstats<<<256, 256>>>(2, NAB * FDIM, NAG, 1);
    k_colstats<<<256, 256>>>(0, 0, NAB, 2);
    k_colstats<<<256, 256>>>(0, NAB * FDIM, NAG, 3);

    // out_ab then out_ag
    k_head<<<NAB, 256>>>(0, 0, 0, 2, g2, be2, W_fc, b_fc, out, NAB);
    k_head<<<NAG, 256>>>(NAB * FDIM, NAB * FDIM, 1, 3, ag_g2, ag_be2, W_agfc, b_agfc,
                         out + NAB, NAG);
}

// round 7
// speedup vs baseline: 1.2361x; 1.1915x over previous
#include <cuda_runtime.h>

#define NAB 20000
#define NAG 20000
#define NTOT 40000
#define FDIM 256
#define EAB 320000
#define EAG 320000
#define ED 640000
#define EPSV 1e-5f

// ---------------- scratch (device globals; no allocs) ----------------
__device__ float g_h[NTOT * FDIM];    // 0: [h_ab ; h_ag], kept for final heads
__device__ float g_xa[NTOT * FDIM];   // 1: GAT1 output
__device__ float g_xb[NTOT * FDIM];   // 2: GAT2 output
__device__ float g_tmp[NTOT * FDIM];  // 3: h = x @ W scratch
__device__ float g_deg[NTOT];         // dinv for GCN
__device__ float g_es[NTOT];
__device__ float g_ed[NTOT];
__device__ float g_csum[4][FDIM];
__device__ float g_csq[4][FDIM];
// CSR scratch
__device__ int g_cnt[NTOT];
__device__ int g_row[NTOT + 1];
__device__ int g_srt[ED];

__device__ __forceinline__ float* BUF(int which) {
    switch (which) {
        case 0: return g_h;
        case 1: return g_xa;
        case 2: return g_xb;
        default: return g_tmp;
    }
}

__device__ __forceinline__ float lrelu(float x) { return x > 0.f ? x : 0.2f * x; }

// ---------------- CSR build ----------------
__global__ void k_zero_cnt(int n) {
    int i = blockIdx.x * blockDim.x + threadIdx.x;
    if (i < n) g_cnt[i] = 0;
}
__global__ void k_hist(const int* __restrict__ dst, int ne) {
    int e = blockIdx.x * blockDim.x + threadIdx.x;
    if (e < ne) atomicAdd(&g_cnt[dst[e]], 1);
}
// dinv from counts (GCN only): deg = cnt + 1 (self loop)
__global__ void k_dinv(int n) {
    int i = blockIdx.x * blockDim.x + threadIdx.x;
    if (i < n) g_deg[i] = rsqrtf((float)(g_cnt[i] + 1));
}
// single-block exclusive scan of g_cnt[0..n) -> g_row
__global__ void k_scan(int n, int ne) {
    __shared__ int part[1024];
    int t = threadIdx.x;
    int chunk = (n + 1023) / 1024;
    int lo = t * chunk;
    int hi = min(lo + chunk, n);
    int s = 0;
    for (int i = lo; i < hi; i++) s += g_cnt[i];
    part[t] = s;
    __syncthreads();
    for (int o = 1; o < 1024; o <<= 1) {
        int v = (t >= o) ? part[t - o] : 0;
        __syncthreads();
        part[t] += v;
        __syncthreads();
    }
    int base = (t == 0) ? 0 : part[t - 1];
    for (int i = lo; i < hi; i++) {
        int c = g_cnt[i];
        g_row[i] = base;
        base += c;
    }
    if (hi >= n) g_row[n] = ne;
}
__global__ void k_fill(const int* __restrict__ src, const int* __restrict__ dst, int ne) {
    int e = blockIdx.x * blockDim.x + threadIdx.x;
    if (e < ne) {
        int d = dst[e];
        int pos = g_row[d] + atomicAdd(&g_cnt[d], 1);
        g_srt[pos] = src[e];
    }
}

// ---------------- GEMM: g_tmp[M,256] = A[M,256] @ B[256,256] ----------------
__global__ void __launch_bounds__(256, 2)
k_gemm(const float* __restrict__ Aext, int awhich, const float* __restrict__ B, int M) {
    const float* A = (awhich < 0) ? Aext : BUF(awhich);
    __shared__ float As[8][128];  // k-major
    __shared__ float Bs[8][128];
    int t = threadIdx.x;
    int tx = t & 15, ty = t >> 4;
    int brow0 = blockIdx.y * 128;
    int bcol0 = blockIdx.x * 128;
    int arow = t >> 1;
    int acol = (t & 1) << 2;
    int bkr = t >> 5;
    int bcl = (t & 31) << 2;
    float acc[8][8];
#pragma unroll
    for (int i = 0; i < 8; i++)
#pragma unroll
        for (int j = 0; j < 8; j++) acc[i][j] = 0.f;

    for (int k0 = 0; k0 < 256; k0 += 8) {
        float4 av = make_float4(0.f, 0.f, 0.f, 0.f);
        int gr = brow0 + arow;
        if (gr < M) av = *(const float4*)(A + gr * 256 + k0 + acol);
        As[acol + 0][arow] = av.x;
        As[acol + 1][arow] = av.y;
        As[acol + 2][arow] = av.z;
        As[acol + 3][arow] = av.w;
        *(float4*)&Bs[bkr][bcl] = *(const float4*)(B + (k0 + bkr) * 256 + bcol0 + bcl);
        __syncthreads();
#pragma unroll
        for (int kk = 0; kk < 8; kk++) {
            float ar[8], br[8];
            *(float4*)(ar + 0) = *(float4*)&As[kk][ty * 8 + 0];
            *(float4*)(ar + 4) = *(float4*)&As[kk][ty * 8 + 4];
            *(float4*)(br + 0) = *(float4*)&Bs[kk][tx * 8 + 0];
            *(float4*)(br + 4) = *(float4*)&Bs[kk][tx * 8 + 4];
#pragma unroll
            for (int i = 0; i < 8; i++)
#pragma unroll
                for (int j = 0; j < 8; j++) acc[i][j] += ar[i] * br[j];
        }
        __syncthreads();
    }
#pragma unroll
    for (int i = 0; i < 8; i++) {
        int row = brow0 + ty * 8 + i;
        if (row < M) {
            *(float4*)(g_tmp + row * 256 + bcol0 + tx * 8 + 0) =
                make_float4(acc[i][0], acc[i][1], acc[i][2], acc[i][3]);
            *(float4*)(g_tmp + row * 256 + bcol0 + tx * 8 + 4) =
                make_float4(acc[i][4], acc[i][5], acc[i][6], acc[i][7]);
        }
    }
}

// ---------------- GCN pull: warp per dst ----------------
__global__ void k_gcn_pull(const float* __restrict__ b, int outoff, int n) {
    int w = (blockIdx.x * blockDim.x + threadIdx.x) >> 5;
    int lane = threadIdx.x & 31;
    if (w >= n) return;
    int r0 = g_row[w], r1 = g_row[w + 1];
    float dd = g_deg[w];
    const float4* hp = (const float4*)(g_tmp + (long)w * FDIM);
    float4 a0 = hp[lane];
    float4 a1 = hp[lane + 32];
    float sc = dd * dd;
    a0.x *= sc; a0.y *= sc; a0.z *= sc; a0.w *= sc;
    a1.x *= sc; a1.y *= sc; a1.z *= sc; a1.w *= sc;
    for (int j = r0; j < r1; j++) {
        int s = g_srt[j];
        float nm = g_deg[s] * dd;
        const float4* sp = (const float4*)(g_tmp + (long)s * FDIM);
        float4 v0 = sp[lane];
        float4 v1 = sp[lane + 32];
        a0.x += v0.x * nm; a0.y += v0.y * nm; a0.z += v0.z * nm; a0.w += v0.w * nm;
        a1.x += v1.x * nm; a1.y += v1.y * nm; a1.z += v1.z * nm; a1.w += v1.w * nm;
    }
    float4 b0 = *((const float4*)b + lane);
    float4 b1 = *((const float4*)b + lane + 32);
    a0.x += b0.x; a0.y += b0.y; a0.z += b0.z; a0.w += b0.w;
    a1.x += b1.x; a1.y += b1.y; a1.z += b1.z; a1.w += b1.w;
    float4* op = (float4*)(g_h + outoff + (long)w * FDIM);
    op[lane] = a0;
    op[lane + 32] = a1;
}

// ---------------- BN ----------------
__global__ void k_zero_stats() {
    g_csum[blockIdx.x][threadIdx.x] = 0.f;
    g_csq[blockIdx.x][threadIdx.x] = 0.f;
}
__global__ void k_colstats(int which, int off, int nrows, int slot) {
    const float* x = BUF(which) + off;
    int col = threadIdx.x;
    float s = 0.f, q = 0.f;
    for (int r = blockIdx.x; r < nrows; r += gridDim.x) {
        float v = x[r * FDIM + col];
        s += v;
        q += v * v;
    }
    atomicAdd(&g_csum[slot][col], s);
    atomicAdd(&g_csq[slot][col], q);
}
__global__ void k_bn_relu(int which, int off, int nrows, int slot,
                          const float* __restrict__ g, const float* __restrict__ be) {
    float* x = BUF(which) + off;
    int idx = blockIdx.x * blockDim.x + threadIdx.x;  // float4 index
    if (idx < nrows * 64) {
        int f = (idx & 63) << 2;
        float n = (float)nrows;
        float4 v = *((float4*)x + idx);
        float* pv = &v.x;
#pragma unroll
        for (int j = 0; j < 4; j++) {
            float mu = g_csum[slot][f + j] / n;
            float var = g_csq[slot][f + j] / n - mu * mu;
            float o = (pv[j] - mu) * rsqrtf(var + EPSV) * g[f + j] + be[f + j];
            pv[j] = o > 0.f ? o : 0.f;
        }
        *((float4*)x + idx) = v;
    }
}

// ---------------- GAT ----------------
// per-node dot products, one warp per node
__global__ void k_dots(const float* __restrict__ a_s, const float* __restrict__ a_d) {
    int w = (blockIdx.x * blockDim.x + threadIdx.x) >> 5;
    int lane = threadIdx.x & 31;
    if (w >= NTOT) return;
    const float4* hp = (const float4*)(g_tmp + (long)w * FDIM);
    const float4* ap = (const float4*)a_s;
    const float4* dp = (const float4*)a_d;
    float s = 0.f, d = 0.f;
#pragma unroll
    for (int c = 0; c < 2; c++) {
        float4 hv = hp[lane + c * 32];
        float4 av = ap[lane + c * 32];
        float4 dv = dp[lane + c * 32];
        s += hv.x * av.x + hv.y * av.y + hv.z * av.z + hv.w * av.w;
        d += hv.x * dv.x + hv.y * dv.y + hv.z * dv.z + hv.w * dv.w;
    }
#pragma unroll
    for (int o = 16; o; o >>= 1) {
        s += __shfl_xor_sync(0xFFFFFFFFu, s, o);
        d += __shfl_xor_sync(0xFFFFFFFFu, d, o);
    }
    if (lane == 0) {
        g_es[w] = s;
        g_ed[w] = d;
    }
}
// fused GAT aggregation: warp per dst, two-pass softmax over bucket + self loop
__global__ void k_gat_pull(int accwhich, const float* __restrict__ b, int dorelu) {
    int w = (blockIdx.x * blockDim.x + threadIdx.x) >> 5;
    int lane = threadIdx.x & 31;
    if (w >= NTOT) return;
    int r0 = g_row[w], r1 = g_row[w + 1];
    float edd = g_ed[w];
    float eself = lrelu(g_es[w] + edd);
    // pass 1: max logit
    float m = eself;
    for (int j = r0 + lane; j < r1; j += 32) {
        m = fmaxf(m, lrelu(g_es[g_srt[j]] + edd));
    }
#pragma unroll
    for (int o = 16; o; o >>= 1) m = fmaxf(m, __shfl_xor_sync(0xFFFFFFFFu, m, o));
    // pass 2: accumulate
    float exs = __expf(eself - m);
    float ssum = exs;
    const float4* hp = (const float4*)(g_tmp + (long)w * FDIM);
    float4 a0 = hp[lane];
    float4 a1 = hp[lane + 32];
    a0.x *= exs; a0.y *= exs; a0.z *= exs; a0.w *= exs;
    a1.x *= exs; a1.y *= exs; a1.z *= exs; a1.w *= exs;
    for (int j = r0; j < r1; j++) {
        int s = g_srt[j];
        float ex = __expf(lrelu(g_es[s] + edd) - m);
        ssum += ex;
        const float4* sp = (const float4*)(g_tmp + (long)s * FDIM);
        float4 v0 = sp[lane];
        float4 v1 = sp[lane + 32];
        a0.x += v0.x * ex; a0.y += v0.y * ex; a0.z += v0.z * ex; a0.w += v0.w * ex;
        a1.x += v1.x * ex; a1.y += v1.y * ex; a1.z += v1.z * ex; a1.w += v1.w * ex;
    }
    float inv = 1.0f / ssum;
    float4 b0 = *((const float4*)b + lane);
    float4 b1 = *((const float4*)b + lane + 32);
    a0.x = a0.x * inv + b0.x; a0.y = a0.y * inv + b0.y;
    a0.z = a0.z * inv + b0.z; a0.w = a0.w * inv + b0.w;
    a1.x = a1.x * inv + b1.x; a1.y = a1.y * inv + b1.y;
    a1.z = a1.z * inv + b1.z; a1.w = a1.w * inv + b1.w;
    if (dorelu) {
        a0.x = fmaxf(a0.x, 0.f); a0.y = fmaxf(a0.y, 0.f);
        a0.z = fmaxf(a0.z, 0.f); a0.w = fmaxf(a0.w, 0.f);
        a1.x = fmaxf(a1.x, 0.f); a1.y = fmaxf(a1.y, 0.f);
        a1.z = fmaxf(a1.z, 0.f); a1.w = fmaxf(a1.w, 0.f);
    }
    float4* op = (float4*)(BUF(accwhich) + (long)w * FDIM);
    op[lane] = a0;
    op[lane + 32] = a1;
}

// ---------------- final heads: relu(bn(cat[x,h])) @ W + b ----------------
__global__ void k_head(int xoff, int hoff, int slot_x, int slot_h,
                       const float* __restrict__ g, const float* __restrict__ be,
                       const float* __restrict__ W, const float* __restrict__ b,
                       float* __restrict__ out, int nrows) {
    __shared__ float red[8];
    const float* xpart = g_xb + xoff;
    const float* hpart = g_h + hoff;
    int row = blockIdx.x;
    int t = threadIdx.x;
    int lane = t & 31, wid = t >> 5;
    float n = (float)nrows;
    float mu1 = g_csum[slot_x][t] / n;
    float var1 = g_csq[slot_x][t] / n - mu1 * mu1;
    float v1 = (xpart[row * FDIM + t] - mu1) * rsqrtf(var1 + EPSV) * g[t] + be[t];
    v1 = v1 > 0.f ? v1 : 0.f;
    float mu2 = g_csum[slot_h][t] / n;
    float var2 = g_csq[slot_h][t] / n - mu2 * mu2;
    float v2 = (hpart[row * FDIM + t] - mu2) * rsqrtf(var2 + EPSV) * g[FDIM + t] + be[FDIM + t];
    v2 = v2 > 0.f ? v2 : 0.f;
    float p = v1 * W[t] + v2 * W[FDIM + t];
#pragma unroll
    for (int o = 16; o; o >>= 1) p += __shfl_xor_sync(0xFFFFFFFFu, p, o);
    if (lane == 0) red[wid] = p;
    __syncthreads();
    if (t == 0) {
        float acc = red[0];
#pragma unroll
        for (int i = 1; i < 8; i++) acc += red[i];
        out[row] = acc + b[0];
    }
}

// ---------------- host orchestration (launches ONLY) ----------------
static void build_csr(const int* src, const int* dst, int ne, int n, int want_dinv) {
    k_zero_cnt<<<(n + 255) / 256, 256>>>(n);
    k_hist<<<(ne + 255) / 256, 256>>>(dst, ne);
    if (want_dinv) k_dinv<<<(n + 255) / 256, 256>>>(n);
    k_scan<<<1, 1024>>>(n, ne);
    k_zero_cnt<<<(n + 255) / 256, 256>>>(n);
    k_fill<<<(ne + 255) / 256, 256>>>(src, dst, ne);
}

static void run_gcn(const float* x, const float* W, const float* b, const int* src,
                    const int* dst, int ne, int n, const float* g, const float* be,
                    int outoff) {
    build_csr(src, dst, ne, n, 1);
    dim3 gg(2, (n + 127) / 128);
    k_gemm<<<gg, 256>>>(x, -1, W, n);
    k_gcn_pull<<<(n + 7) / 8, 256>>>(b, outoff, n);
    k_zero_stats<<<1, 256>>>();
    k_colstats<<<256, 256>>>(0, outoff, n, 0);
    k_bn_relu<<<(n * 64 + 255) / 256, 256>>>(0, outoff, n, 0, g, be);
}

static void run_gat(int inwhich, const float* W, const float* a_s, const float* a_d,
                    const float* b, int accwhich, int dorelu) {
    dim3 gg(2, (NTOT + 127) / 128);
    k_gemm<<<gg, 256>>>(nullptr, inwhich, W, NTOT);
    k_dots<<<(NTOT + 7) / 8, 256>>>(a_s, a_d);
    k_gat_pull<<<(NTOT + 7) / 8, 256>>>(accwhich, b, dorelu);
}

extern "C" void kernel_launch(void* const* d_in, const int* in_sizes, int n_in, void* d_out,
                              int out_size) {
    const float* x_ab = (const float*)d_in[0];
    const float* x_ag = (const float*)d_in[1];
    const float* W_gcn = (const float*)d_in[2];
    const float* b_gcn = (const float*)d_in[3];
    const float* g1 = (const float*)d_in[4];
    const float* be1 = (const float*)d_in[5];
    const float* W_aggcn = (const float*)d_in[6];
    const float* b_aggcn = (const float*)d_in[7];
    const float* ag_g1 = (const float*)d_in[8];
    const float* ag_be1 = (const float*)d_in[9];
    const float* W_gat = (const float*)d_in[10];
    const float* a_src = (const float*)d_in[11];
    const float* a_dst = (const float*)d_in[12];
    const float* b_gat = (const float*)d_in[13];
    const float* W_gat2 = (const float*)d_in[14];
    const float* a_src2 = (const float*)d_in[15];
    const float* a_dst2 = (const float*)d_in[16];
    const float* b_gat2 = (const float*)d_in[17];
    const float* ag_g2 = (const float*)d_in[18];
    const float* ag_be2 = (const float*)d_in[19];
    const float* W_agfc = (const float*)d_in[20];
    const float* b_agfc = (const float*)d_in[21];
    const float* g2 = (const float*)d_in[22];
    const float* be2 = (const float*)d_in[23];
    const float* W_fc = (const float*)d_in[24];
    const float* b_fc = (const float*)d_in[25];
    const int* e_ab = (const int*)d_in[26];
    const int* e_ag = (const int*)d_in[27];
    const int* e_d = (const int*)d_in[28];
    float* out = (float*)d_out;

    // GCN on AB graph -> g_h rows [0, NAB)
    run_gcn(x_ab, W_gcn, b_gcn, e_ab, e_ab + EAB, EAB, NAB, g1, be1, 0);
    // GCN on AG graph -> g_h rows [NAB, NTOT)
    run_gcn(x_ag, W_aggcn, b_aggcn, e_ag, e_ag + EAG, EAG, NAG, ag_g1, ag_be1, NAB * FDIM);

    // CSR for the D graph (shared by both GAT layers)
    build_csr(e_d, e_d + ED, ED, NTOT, 0);
    // GAT layer 1: g_h(0) -> g_xa(1), relu
    run_gat(0, W_gat, a_src, a_dst, b_gat, 1, 1);
    // GAT layer 2: g_xa(1) -> g_xb(2), no relu
    run_gat(1, W_gat2, a_src2, a_dst2, b_gat2, 2, 0);

    // head stats: x1, x2, h_ab, h_ag
    k_zero_stats<<<4, 256>>>();
    k_colstats<<<256, 256>>>(2, 0, NAB, 0);
    k_colstats<<<256, 256>>>(2, NAB * FDIM, NAG, 1);
    k_colstats<<<256, 256>>>(0, 0, NAB, 2);
    k_colstats<<<256, 256>>>(0, NAB * FDIM, NAG, 3);

    // out_ab then out_ag
    k_head<<<NAB, 256>>>(0, 0, 0, 2, g2, be2, W_fc, b_fc, out, NAB);
    k_head<<<NAG, 256>>>(NAB * FDIM, NAB * FDIM, 1, 3, ag_g2, ag_be2, W_agfc, b_agfc,
                         out + NAB, NAG);
}

// round 9
// speedup vs baseline: 1.7897x; 1.4479x over previous
#include <cuda_runtime.h>

#define NAB 20000
#define NAG 20000
#define NTOT 40000
#define FDIM 256
#define EAB 320000
#define EAG 320000
#define ED 640000
#define EPSV 1e-5f

// ---------------- scratch (device globals; no allocs) ----------------
__device__ float g_h[NTOT * FDIM];    // 0: [h_ab ; h_ag], kept for final heads
__device__ float g_xa[NTOT * FDIM];   // 1: GAT1 output
__device__ float g_xb[NTOT * FDIM];   // 2: GAT2 output
__device__ float g_tmp[NTOT * FDIM];  // 3: h = x @ W scratch
__device__ float g_deg[NTOT];         // dinv: [0,20000) graph0, [20000,40000) graph1
__device__ float g_es[NTOT];
__device__ float g_ed[NTOT];
__device__ float g_csum[4][FDIM];
__device__ float g_csq[4][FDIM];
// CSR scratch: 3 graphs. cnt base g*NTOT, row base g*(NTOT+1), srt bases 0/EAB/EAB+EAG
__device__ int g_cnt[3 * NTOT];
__device__ int g_row[3 * (NTOT + 1)];
__device__ int g_srt[EAB + EAG + ED];

__device__ __forceinline__ float* BUF(int which) {
    switch (which) {
        case 0: return g_h;
        case 1: return g_xa;
        case 2: return g_xb;
        default: return g_tmp;
    }
}

__device__ __forceinline__ float lrelu(float x) { return x > 0.f ? x : 0.2f * x; }

// ---------------- batched CSR build ----------------
__global__ void k_zero_csr() {
    int i = blockIdx.x * blockDim.x + threadIdx.x;
    if (i < 3 * NTOT) g_cnt[i] = 0;
}
__global__ void k_hist_all(const int* __restrict__ dab, const int* __restrict__ dag,
                           const int* __restrict__ dd) {
    int e = blockIdx.x * blockDim.x + threadIdx.x;
    if (e < EAB) atomicAdd(&g_cnt[0 * NTOT + dab[e]], 1);
    else if (e < EAB + EAG) atomicAdd(&g_cnt[1 * NTOT + dag[e - EAB]], 1);
    else if (e < EAB + EAG + ED) atomicAdd(&g_cnt[2 * NTOT + dd[e - EAB - EAG]], 1);
}
__global__ void k_dinv_all() {
    int i = blockIdx.x * blockDim.x + threadIdx.x;
    if (i < NTOT) {
        int c = (i < NAB) ? g_cnt[i] : g_cnt[NTOT + (i - NAB)];
        g_deg[i] = rsqrtf((float)(c + 1));
    }
}
// 3 blocks, one per graph; warp-shuffle two-level scan
__global__ void k_scan_all() {
    __shared__ int warpsum[32];
    int g = blockIdx.x;
    int n = (g == 2) ? NTOT : NAB;
    int ne = (g == 2) ? ED : EAB;
    int cb = g * NTOT;
    int rb = g * (NTOT + 1);
    int t = threadIdx.x;
    int lane = t & 31, wid = t >> 5;
    int chunk = (n + 1023) / 1024;
    int lo = t * chunk;
    int hi = min(lo + chunk, n);
    int s = 0;
    for (int i = lo; i < hi; i++) s += g_cnt[cb + i];
    // inclusive warp scan
    int v = s;
#pragma unroll
    for (int o = 1; o < 32; o <<= 1) {
        int u = __shfl_up_sync(0xFFFFFFFFu, v, o);
        if (lane >= o) v += u;
    }
    if (lane == 31) warpsum[wid] = v;
    __syncthreads();
    if (wid == 0) {
        int w = warpsum[lane];
#pragma unroll
        for (int o = 1; o < 32; o <<= 1) {
            int u = __shfl_up_sync(0xFFFFFFFFu, w, o);
            if (lane >= o) w += u;
        }
        warpsum[lane] = w;
    }
    __syncthreads();
    int base = v - s + (wid > 0 ? warpsum[wid - 1] : 0);  // exclusive prefix
    for (int i = lo; i < hi; i++) {
        g_row[rb + i] = base;
        base += g_cnt[cb + i];
    }
    if (t == 0) g_row[rb + n] = ne;
}
__global__ void k_fill_all(const int* __restrict__ eab, const int* __restrict__ eag,
                           const int* __restrict__ ed) {
    int e = blockIdx.x * blockDim.x + threadIdx.x;
    int g, le, sb;
    const int* src;
    const int* dst;
    if (e < EAB) { g = 0; le = e; src = eab; dst = eab + EAB; sb = 0; }
    else if (e < EAB + EAG) { g = 1; le = e - EAB; src = eag; dst = eag + EAG; sb = EAB; }
    else if (e < EAB + EAG + ED) { g = 2; le = e - EAB - EAG; src = ed; dst = ed + ED; sb = EAB + EAG; }
    else return;
    int d = dst[le];
    int pos = g_row[g * (NTOT + 1) + d] + atomicAdd(&g_cnt[g * NTOT + d], 1);
    g_srt[sb + pos] = src[le];
}

// ---------------- GEMM: g_tmp[M,256] = A[M,256] @ B[256,256] ----------------
// double-buffered 128x128x8, 8x8/thread; optional fused dual dot products
__global__ void __launch_bounds__(256, 2)
k_gemm(const float* __restrict__ Aext, int awhich, const float* __restrict__ B, int M,
       const float* __restrict__ a_s, const float* __restrict__ a_d) {
    const float* A = (awhich < 0) ? Aext : BUF(awhich);
    __shared__ float As[2][8][128];  // k-major
    __shared__ float Bs[2][8][128];
    int t = threadIdx.x;
    int tx = t & 15, ty = t >> 4;
    int brow0 = blockIdx.y * 128;
    int bcol0 = blockIdx.x * 128;
    int arow = t >> 1;
    int acol = (t & 1) << 2;
    int bkr = t >> 5;
    int bcl = (t & 31) << 2;
    float acc[8][8];
#pragma unroll
    for (int i = 0; i < 8; i++)
#pragma unroll
        for (int j = 0; j < 8; j++) acc[i][j] = 0.f;

    // prologue: tile 0
    {
        float4 av = make_float4(0.f, 0.f, 0.f, 0.f);
        int gr = brow0 + arow;
        if (gr < M) av = *(const float4*)(A + gr * 256 + acol);
        As[0][acol + 0][arow] = av.x;
        As[0][acol + 1][arow] = av.y;
        As[0][acol + 2][arow] = av.z;
        As[0][acol + 3][arow] = av.w;
        *(float4*)&Bs[0][bkr][bcl] = *(const float4*)(B + bkr * 256 + bcol0 + bcl);
    }
    __syncthreads();
    int cur = 0;
    for (int k0 = 8; k0 <= 256; k0 += 8) {
        float4 av2, bv2;
        if (k0 < 256) {
            av2 = make_float4(0.f, 0.f, 0.f, 0.f);
            int gr = brow0 + arow;
            if (gr < M) av2 = *(const float4*)(A + gr * 256 + k0 + acol);
            bv2 = *(const float4*)(B + (k0 + bkr) * 256 + bcol0 + bcl);
        }
#pragma unroll
        for (int kk = 0; kk < 8; kk++) {
            float ar[8], br[8];
            *(float4*)(ar + 0) = *(float4*)&As[cur][kk][ty * 8 + 0];
            *(float4*)(ar + 4) = *(float4*)&As[cur][kk][ty * 8 + 4];
            *(float4*)(br + 0) = *(float4*)&Bs[cur][kk][tx * 8 + 0];
            *(float4*)(br + 4) = *(float4*)&Bs[cur][kk][tx * 8 + 4];
#pragma unroll
            for (int i = 0; i < 8; i++)
#pragma unroll
                for (int j = 0; j < 8; j++) acc[i][j] += ar[i] * br[j];
        }
        if (k0 < 256) {
            int nxt = cur ^ 1;
            As[nxt][acol + 0][arow] = av2.x;
            As[nxt][acol + 1][arow] = av2.y;
            As[nxt][acol + 2][arow] = av2.z;
            As[nxt][acol + 3][arow] = av2.w;
            *(float4*)&Bs[nxt][bkr][bcl] = bv2;
            __syncthreads();
            cur = nxt;
        }
    }
#pragma unroll
    for (int i = 0; i < 8; i++) {
        int row = brow0 + ty * 8 + i;
        if (row < M) {
            *(float4*)(g_tmp + row * 256 + bcol0 + tx * 8 + 0) =
                make_float4(acc[i][0], acc[i][1], acc[i][2], acc[i][3]);
            *(float4*)(g_tmp + row * 256 + bcol0 + tx * 8 + 4) =
                make_float4(acc[i][4], acc[i][5], acc[i][6], acc[i][7]);
        }
    }
    // fused GAT dot products: es += h.a_s, ed += h.a_d over this col tile
    if (a_s) {
        float as[8], ad[8];
#pragma unroll
        for (int j = 0; j < 8; j++) {
            as[j] = a_s[bcol0 + tx * 8 + j];
            ad[j] = a_d[bcol0 + tx * 8 + j];
        }
#pragma unroll
        for (int i = 0; i < 8; i++) {
            float ps = 0.f, pd = 0.f;
#pragma unroll
            for (int j = 0; j < 8; j++) {
                ps += acc[i][j] * as[j];
                pd += acc[i][j] * ad[j];
            }
#pragma unroll
            for (int o = 8; o; o >>= 1) {
                ps += __shfl_xor_sync(0xFFFFFFFFu, ps, o);
                pd += __shfl_xor_sync(0xFFFFFFFFu, pd, o);
            }
            int row = brow0 + ty * 8 + i;
            if (tx == 0 && row < M) {
                atomicAdd(&g_es[row], ps);
                atomicAdd(&g_ed[row], pd);
            }
        }
    }
}

__global__ void k_zero_esed() {
    int i = blockIdx.x * blockDim.x + threadIdx.x;
    if (i < NTOT) {
        g_es[i] = 0.f;
        g_ed[i] = 0.f;
    }
}

// ---------------- GCN pull: warp per dst ----------------
__global__ void k_gcn_pull(const float* __restrict__ b, int outoff, int n, int g,
                           int srtbase, int degoff) {
    int w = (blockIdx.x * blockDim.x + threadIdx.x) >> 5;
    int lane = threadIdx.x & 31;
    if (w >= n) return;
    int rb = g * (NTOT + 1);
    int r0 = g_row[rb + w], r1 = g_row[rb + w + 1];
    float dd = g_deg[degoff + w];
    const float4* hp = (const float4*)(g_tmp + (long)w * FDIM);
    float4 a0 = hp[lane];
    float4 a1 = hp[lane + 32];
    float sc = dd * dd;
    a0.x *= sc; a0.y *= sc; a0.z *= sc; a0.w *= sc;
    a1.x *= sc; a1.y *= sc; a1.z *= sc; a1.w *= sc;
    for (int j = r0; j < r1; j++) {
        int s = g_srt[srtbase + j];
        float nm = g_deg[degoff + s] * dd;
        const float4* sp = (const float4*)(g_tmp + (long)s * FDIM);
        float4 v0 = sp[lane];
        float4 v1 = sp[lane + 32];
        a0.x += v0.x * nm; a0.y += v0.y * nm; a0.z += v0.z * nm; a0.w += v0.w * nm;
        a1.x += v1.x * nm; a1.y += v1.y * nm; a1.z += v1.z * nm; a1.w += v1.w * nm;
    }
    float4 b0 = *((const float4*)b + lane);
    float4 b1 = *((const float4*)b + lane + 32);
    a0.x += b0.x; a0.y += b0.y; a0.z += b0.z; a0.w += b0.w;
    a1.x += b1.x; a1.y += b1.y; a1.z += b1.z; a1.w += b1.w;
    float4* op = (float4*)(g_h + outoff + (long)w * FDIM);
    op[lane] = a0;
    op[lane + 32] = a1;
}

// ---------------- BN ----------------
__global__ void k_zero_stats() {
    g_csum[blockIdx.x][threadIdx.x] = 0.f;
    g_csq[blockIdx.x][threadIdx.x] = 0.f;
}
__global__ void k_colstats(int which, int off, int nrows, int slot) {
    const float* x = BUF(which) + off;
    int col = threadIdx.x;
    float s = 0.f, q = 0.f;
    for (int r = blockIdx.x; r < nrows; r += gridDim.x) {
        float v = x[r * FDIM + col];
        s += v;
        q += v * v;
    }
    atomicAdd(&g_csum[slot][col], s);
    atomicAdd(&g_csq[slot][col], q);
}
__global__ void k_bn_relu(int which, int off, int nrows, int slot,
                          const float* __restrict__ g, const float* __restrict__ be) {
    float* x = BUF(which) + off;
    int idx = blockIdx.x * blockDim.x + threadIdx.x;  // float4 index
    if (idx < nrows * 64) {
        int f = (idx & 63) << 2;
        float n = (float)nrows;
        float4 v = *((float4*)x + idx);
        float* pv = &v.x;
#pragma unroll
        for (int j = 0; j < 4; j++) {
            float mu = g_csum[slot][f + j] / n;
            float var = g_csq[slot][f + j] / n - mu * mu;
            float o = (pv[j] - mu) * rsqrtf(var + EPSV) * g[f + j] + be[f + j];
            pv[j] = o > 0.f ? o : 0.f;
        }
        *((float4*)x + idx) = v;
    }
}

// ---------------- fused GAT aggregation: warp per dst ----------------
__global__ void k_gat_pull(int accwhich, const float* __restrict__ b, int dorelu) {
    int w = (blockIdx.x * blockDim.x + threadIdx.x) >> 5;
    int lane = threadIdx.x & 31;
    if (w >= NTOT) return;
    int rb = 2 * (NTOT + 1);
    int sb = EAB + EAG;
    int r0 = g_row[rb + w], r1 = g_row[rb + w + 1];
    float edd = g_ed[w];
    float eself = lrelu(g_es[w] + edd);
    // pass 1: max logit
    float m = eself;
    for (int j = r0 + lane; j < r1; j += 32) {
        m = fmaxf(m, lrelu(g_es[g_srt[sb + j]] + edd));
    }
#pragma unroll
    for (int o = 16; o; o >>= 1) m = fmaxf(m, __shfl_xor_sync(0xFFFFFFFFu, m, o));
    // pass 2: accumulate
    float exs = __expf(eself - m);
    float ssum = exs;
    const float4* hp = (const float4*)(g_tmp + (long)w * FDIM);
    float4 a0 = hp[lane];
    float4 a1 = hp[lane + 32];
    a0.x *= exs; a0.y *= exs; a0.z *= exs; a0.w *= exs;
    a1.x *= exs; a1.y *= exs; a1.z *= exs; a1.w *= exs;
    for (int j = r0; j < r1; j++) {
        int s = g_srt[sb + j];
        float ex = __expf(lrelu(g_es[s] + edd) - m);
        ssum += ex;
        const float4* sp = (const float4*)(g_tmp + (long)s * FDIM);
        float4 v0 = sp[lane];
        float4 v1 = sp[lane + 32];
        a0.x += v0.x * ex; a0.y += v0.y * ex; a0.z += v0.z * ex; a0.w += v0.w * ex;
        a1.x += v1.x * ex; a1.y += v1.y * ex; a1.z += v1.z * ex; a1.w += v1.w * ex;
    }
    float inv = 1.0f / ssum;
    float4 b0 = *((const float4*)b + lane);
    float4 b1 = *((const float4*)b + lane + 32);
    a0.x = a0.x * inv + b0.x; a0.y = a0.y * inv + b0.y;
    a0.z = a0.z * inv + b0.z; a0.w = a0.w * inv + b0.w;
    a1.x = a1.x * inv + b1.x; a1.y = a1.y * inv + b1.y;
    a1.z = a1.z * inv + b1.z; a1.w = a1.w * inv + b1.w;
    if (dorelu) {
        a0.x = fmaxf(a0.x, 0.f); a0.y = fmaxf(a0.y, 0.f);
        a0.z = fmaxf(a0.z, 0.f); a0.w = fmaxf(a0.w, 0.f);
        a1.x = fmaxf(a1.x, 0.f); a1.y = fmaxf(a1.y, 0.f);
        a1.z = fmaxf(a1.z, 0.f); a1.w = fmaxf(a1.w, 0.f);
    }
    float4* op = (float4*)(BUF(accwhich) + (long)w * FDIM);
    op[lane] = a0;
    op[lane + 32] = a1;
}

// ---------------- final heads: relu(bn(cat[x,h])) @ W + b ----------------
__global__ void k_head(int xoff, int hoff, int slot_x, int slot_h,
                       const float* __restrict__ g, const float* __restrict__ be,
                       const float* __restrict__ W, const float* __restrict__ b,
                       float* __restrict__ out, int nrows) {
    __shared__ float red[8];
    const float* xpart = g_xb + xoff;
    const float* hpart = g_h + hoff;
    int row = blockIdx.x;
    int t = threadIdx.x;
    int lane = t & 31, wid = t >> 5;
    float n = (float)nrows;
    float mu1 = g_csum[slot_x][t] / n;
    float var1 = g_csq[slot_x][t] / n - mu1 * mu1;
    float v1 = (xpart[row * FDIM + t] - mu1) * rsqrtf(var1 + EPSV) * g[t] + be[t];
    v1 = v1 > 0.f ? v1 : 0.f;
    float mu2 = g_csum[slot_h][t] / n;
    float var2 = g_csq[slot_h][t] / n - mu2 * mu2;
    float v2 = (hpart[row * FDIM + t] - mu2) * rsqrtf(var2 + EPSV) * g[FDIM + t] + be[FDIM + t];
    v2 = v2 > 0.f ? v2 : 0.f;
    float p = v1 * W[t] + v2 * W[FDIM + t];
#pragma unroll
    for (int o = 16; o; o >>= 1) p += __shfl_xor_sync(0xFFFFFFFFu, p, o);
    if (lane == 0) red[wid] = p;
    __syncthreads();
    if (t == 0) {
        float acc = red[0];
#pragma unroll
        for (int i = 1; i < 8; i++) acc += red[i];
        out[row] = acc + b[0];
    }
}

// ---------------- host orchestration (launches ONLY) ----------------
#define ETOT (EAB + EAG + ED)

static void run_gcn(const float* x, const float* W, const float* b, int n, int g,
                    int srtbase, int degoff, const float* gam, const float* be, int outoff) {
    dim3 gg(2, (n + 127) / 128);
    k_gemm<<<gg, 256>>>(x, -1, W, n, nullptr, nullptr);
    k_gcn_pull<<<(n + 7) / 8, 256>>>(b, outoff, n, g, srtbase, degoff);
    k_zero_stats<<<1, 256>>>();
    k_colstats<<<256, 256>>>(0, outoff, n, 0);
    k_bn_relu<<<(n * 64 + 255) / 256, 256>>>(0, outoff, n, 0, gam, be);
}

static void run_gat(int inwhich, const float* W, const float* a_s, const float* a_d,
                    const float* b, int accwhich, int dorelu) {
    k_zero_esed<<<(NTOT + 255) / 256, 256>>>();
    dim3 gg(2, (NTOT + 127) / 128);
    k_gemm<<<gg, 256>>>(nullptr, inwhich, W, NTOT, a_s, a_d);
    k_gat_pull<<<(NTOT + 7) / 8, 256>>>(accwhich, b, dorelu);
}

extern "C" void kernel_launch(void* const* d_in, const int* in_sizes, int n_in, void* d_out,
                              int out_size) {
    const float* x_ab = (const float*)d_in[0];
    const float* x_ag = (const float*)d_in[1];
    const float* W_gcn = (const float*)d_in[2];
    const float* b_gcn = (const float*)d_in[3];
    const float* g1 = (const float*)d_in[4];
    const float* be1 = (const float*)d_in[5];
    const float* W_aggcn = (const float*)d_in[6];
    const float* b_aggcn = (const float*)d_in[7];
    const float* ag_g1 = (const float*)d_in[8];
    const float* ag_be1 = (const float*)d_in[9];
    const float* W_gat = (const float*)d_in[10];
    const float* a_src = (const float*)d_in[11];
    const float* a_dst = (const float*)d_in[12];
    const float* b_gat = (const float*)d_in[13];
    const float* W_gat2 = (const float*)d_in[14];
    const float* a_src2 = (const float*)d_in[15];
    const float* a_dst2 = (const float*)d_in[16];
    const float* b_gat2 = (const float*)d_in[17];
    const float* ag_g2 = (const float*)d_in[18];
    const float* ag_be2 = (const float*)d_in[19];
    const float* W_agfc = (const float*)d_in[20];
    const float* b_agfc = (const float*)d_in[21];
    const float* g2 = (const float*)d_in[22];
    const float* be2 = (const float*)d_in[23];
    const float* W_fc = (const float*)d_in[24];
    const float* b_fc = (const float*)d_in[25];
    const int* e_ab = (const int*)d_in[26];
    const int* e_ag = (const int*)d_in[27];
    const int* e_d = (const int*)d_in[28];
    float* out = (float*)d_out;

    // batched CSR build for all 3 graphs
    k_zero_csr<<<(3 * NTOT + 255) / 256, 256>>>();
    k_hist_all<<<(ETOT + 255) / 256, 256>>>(e_ab + EAB, e_ag + EAG, e_d + ED);
    k_dinv_all<<<(NTOT + 255) / 256, 256>>>();
    k_scan_all<<<3, 1024>>>();
    k_zero_csr<<<(3 * NTOT + 255) / 256, 256>>>();
    k_fill_all<<<(ETOT + 255) / 256, 256>>>(e_ab, e_ag, e_d);

    // GCN on AB graph -> g_h rows [0, NAB)
    run_gcn(x_ab, W_gcn, b_gcn, NAB, 0, 0, 0, g1, be1, 0);
    // GCN on AG graph -> g_h rows [NAB, NTOT)
    run_gcn(x_ag, W_aggcn, b_aggcn, NAG, 1, EAB, NAB, ag_g1, ag_be1, NAB * FDIM);

    // GAT layer 1: g_h(0) -> g_xa(1), relu
    run_gat(0, W_gat, a_src, a_dst, b_gat, 1, 1);
    // GAT layer 2: g_xa(1) -> g_xb(2), no relu
    run_gat(1, W_gat2, a_src2, a_dst2, b_gat2, 2, 0);

    // head stats: x1, x2, h_ab, h_ag
    k_zero_stats<<<4, 256>>>();
    k_colstats<<<256, 256>>>(2, 0, NAB, 0);
    k_colstats<<<256, 256>>>(2, NAB * FDIM, NAG, 1);
    k_colstats<<<256, 256>>>(0, 0, NAB, 2);
    k_colstats<<<256, 256>>>(0, NAB * FDIM, NAG, 3);

    // out_ab then out_ag
    k_head<<<NAB, 256>>>(0, 0, 0, 2, g2, be2, W_fc, b_fc, out, NAB);
    k_head<<<NAG, 256>>>(NAB * FDIM, NAB * FDIM, 1, 3, ag_g2, ag_be2, W_agfc, b_agfc,
                         out + NAB, NAG);
}

// round 10
// speedup vs baseline: 2.6561x; 1.4841x over previous
#include <cuda_runtime.h>
#include <mma.h>
using namespace nvcuda;

#define NAB 20000
#define NAG 20000
#define NTOT 40000
#define FDIM 256
#define EAB 320000
#define EAG 320000
#define ED 640000
#define ETOT (EAB + EAG + ED)
#define EPSV 1e-5f
#define MPAD 40064  // 313*128, GEMM tile padding
#define CSRN (3 * NTOT)
#define SCAN_BLOCKS ((CSRN + 1023) / 1024)

// ---------------- scratch (device globals; no allocs) ----------------
__device__ float g_h[NTOT * FDIM];    // 0
__device__ float g_xa[NTOT * FDIM];   // 1
__device__ float g_xb[NTOT * FDIM];   // 2
__device__ float g_tmp[MPAD * FDIM];  // 3 (padded for full-tile GEMM stores)
__device__ float g_deg[NTOT];
__device__ float g_es[NTOT];
__device__ float g_ed[NTOT];
__device__ float g_csum[4][FDIM];
__device__ float g_csq[4][FDIM];
// CSR: 3 graphs concatenated; global prefix in g_rowg
__device__ int g_cnt[CSRN];
__device__ int g_rowg[CSRN + 1];
__device__ int g_bsum[SCAN_BLOCKS];
__device__ int g_srt[ETOT];

__device__ __forceinline__ float* BUF(int which) {
    switch (which) {
        case 0: return g_h;
        case 1: return g_xa;
        case 2: return g_xb;
        default: return g_tmp;
    }
}

__device__ __forceinline__ float lrelu(float x) { return x > 0.f ? x : 0.2f * x; }

// ---------------- batched CSR build ----------------
__global__ void k_zero_csr() {
    int i = blockIdx.x * blockDim.x + threadIdx.x;
    if (i < CSRN) g_cnt[i] = 0;
}
__global__ void k_hist_all(const int* __restrict__ dab, const int* __restrict__ dag,
                           const int* __restrict__ dd) {
    int e = blockIdx.x * blockDim.x + threadIdx.x;
    if (e < EAB) atomicAdd(&g_cnt[0 * NTOT + dab[e]], 1);
    else if (e < EAB + EAG) atomicAdd(&g_cnt[1 * NTOT + dag[e - EAB]], 1);
    else if (e < ETOT) atomicAdd(&g_cnt[2 * NTOT + dd[e - EAB - EAG]], 1);
}
__global__ void k_dinv_all() {
    int i = blockIdx.x * blockDim.x + threadIdx.x;
    if (i < NTOT) {
        int c = (i < NAB) ? g_cnt[i] : g_cnt[NTOT + (i - NAB)];
        g_deg[i] = rsqrtf((float)(c + 1));
    }
}
// multi-block scan: part 1 — per-block exclusive scan + block sums
__global__ void k_scan1() {
    __shared__ int wsum[32];
    int gi = blockIdx.x * 1024 + threadIdx.x;
    int v = (gi < CSRN) ? g_cnt[gi] : 0;
    int lane = threadIdx.x & 31, wid = threadIdx.x >> 5;
    int inc = v;
#pragma unroll
    for (int o = 1; o < 32; o <<= 1) {
        int u = __shfl_up_sync(0xFFFFFFFFu, inc, o);
        if (lane >= o) inc += u;
    }
    if (lane == 31) wsum[wid] = inc;
    __syncthreads();
    if (wid == 0) {
        int w = wsum[lane];
#pragma unroll
        for (int o = 1; o < 32; o <<= 1) {
            int u = __shfl_up_sync(0xFFFFFFFFu, w, o);
            if (lane >= o) w += u;
        }
        wsum[lane] = w;
    }
    __syncthreads();
    int ex = inc - v + (wid ? wsum[wid - 1] : 0);
    if (gi < CSRN) g_rowg[gi] = ex;
    if (threadIdx.x == 1023) g_bsum[blockIdx.x] = ex + v;
}
// part 2 — exclusive scan of block sums (1 block, 128 threads)
__global__ void k_scan2() {
    __shared__ int ws[4];
    int t = threadIdx.x;
    int lane = t & 31, wid = t >> 5;
    int v = (t < SCAN_BLOCKS) ? g_bsum[t] : 0;
    int inc = v;
#pragma unroll
    for (int o = 1; o < 32; o <<= 1) {
        int u = __shfl_up_sync(0xFFFFFFFFu, inc, o);
        if (lane >= o) inc += u;
    }
    if (lane == 31) ws[wid] = inc;
    __syncthreads();
    int add = 0;
    for (int i = 0; i < wid; i++) add += ws[i];
    if (t < SCAN_BLOCKS) g_bsum[t] = inc - v + add;
}
// part 3 — add block offsets
__global__ void k_scan3() {
    int gi = blockIdx.x * 1024 + threadIdx.x;
    if (gi < CSRN) g_rowg[gi] += g_bsum[blockIdx.x];
    if (gi == 0) g_rowg[CSRN] = ETOT;
}
__global__ void k_fill_all(const int* __restrict__ eab, const int* __restrict__ eag,
                           const int* __restrict__ ed) {
    int e = blockIdx.x * blockDim.x + threadIdx.x;
    int g, le;
    const int* src;
    const int* dst;
    if (e < EAB) { g = 0; le = e; src = eab; dst = eab + EAB; }
    else if (e < EAB + EAG) { g = 1; le = e - EAB; src = eag; dst = eag + EAG; }
    else if (e < ETOT) { g = 2; le = e - EAB - EAG; src = ed; dst = ed + ED; }
    else return;
    int d = dst[le];
    int pos = g_rowg[g * NTOT + d] + atomicAdd(&g_cnt[g * NTOT + d], 1);
    g_srt[pos] = src[le];
}

// ---------------- TF32 wmma GEMM: g_tmp[M,256] = A[M,256] @ B[256,256] ----------------
__global__ void __launch_bounds__(256, 2)
k_gemm(const float* __restrict__ Aext, int awhich, const float* __restrict__ B, int M) {
    const float* A = (awhich < 0) ? Aext : BUF(awhich);
    __shared__ alignas(16) float As[2][128][16];
    __shared__ alignas(16) float Bs[2][16][128];
    int t = threadIdx.x;
    int wid = t >> 5;
    int wr = wid >> 2;  // 0..1
    int wc = wid & 3;   // 0..3
    int brow0 = blockIdx.y * 128;
    int bcol0 = blockIdx.x * 128;

    wmma::fragment<wmma::accumulator, 16, 16, 8, float> c[4][2];
#pragma unroll
    for (int i = 0; i < 4; i++)
#pragma unroll
        for (int j = 0; j < 2; j++) wmma::fill_fragment(c[i][j], 0.0f);

    int af0 = t * 2, af1 = t * 2 + 1;
    int ar0 = af0 >> 2, ac0 = (af0 & 3) << 2;
    int ar1 = af1 >> 2, ac1 = (af1 & 3) << 2;
    int br0 = af0 >> 5, bc0 = (af0 & 31) << 2;
    int br1 = af1 >> 5, bc1 = (af1 & 31) << 2;

    // prologue: tile 0
    {
        float4 z = make_float4(0.f, 0.f, 0.f, 0.f);
        float4 a0v = (brow0 + ar0 < M) ? *(const float4*)(A + (brow0 + ar0) * 256 + ac0) : z;
        float4 a1v = (brow0 + ar1 < M) ? *(const float4*)(A + (brow0 + ar1) * 256 + ac1) : z;
        *(float4*)&As[0][ar0][ac0] = a0v;
        *(float4*)&As[0][ar1][ac1] = a1v;
        *(float4*)&Bs[0][br0][bc0] = *(const float4*)(B + br0 * 256 + bcol0 + bc0);
        *(float4*)&Bs[0][br1][bc1] = *(const float4*)(B + br1 * 256 + bcol0 + bc1);
    }
    __syncthreads();
    int cur = 0;
    for (int k0 = 16; k0 <= 256; k0 += 16) {
        float4 a0v, a1v, b0v, b1v;
        if (k0 < 256) {
            float4 z = make_float4(0.f, 0.f, 0.f, 0.f);
            a0v = (brow0 + ar0 < M) ? *(const float4*)(A + (brow0 + ar0) * 256 + k0 + ac0) : z;
            a1v = (brow0 + ar1 < M) ? *(const float4*)(A + (brow0 + ar1) * 256 + k0 + ac1) : z;
            b0v = *(const float4*)(B + (k0 + br0) * 256 + bcol0 + bc0);
            b1v = *(const float4*)(B + (k0 + br1) * 256 + bcol0 + bc1);
        }
#pragma unroll
        for (int kk = 0; kk < 16; kk += 8) {
            wmma::fragment<wmma::matrix_a, 16, 16, 8, wmma::precision::tf32, wmma::row_major> a[4];
            wmma::fragment<wmma::matrix_b, 16, 16, 8, wmma::precision::tf32, wmma::row_major> b[2];
#pragma unroll
            for (int i = 0; i < 4; i++) {
                wmma::load_matrix_sync(a[i], &As[cur][wr * 64 + i * 16][kk], 16);
#pragma unroll
                for (int e = 0; e < a[i].num_elements; e++)
                    a[i].x[e] = wmma::__float_to_tf32(a[i].x[e]);
            }
#pragma unroll
            for (int j = 0; j < 2; j++) {
                wmma::load_matrix_sync(b[j], &Bs[cur][kk][wc * 32 + j * 16], 128);
#pragma unroll
                for (int e = 0; e < b[j].num_elements; e++)
                    b[j].x[e] = wmma::__float_to_tf32(b[j].x[e]);
            }
#pragma unroll
            for (int i = 0; i < 4; i++)
#pragma unroll
                for (int j = 0; j < 2; j++) wmma::mma_sync(c[i][j], a[i], b[j], c[i][j]);
        }
        if (k0 < 256) {
            int nxt = cur ^ 1;
            *(float4*)&As[nxt][ar0][ac0] = a0v;
            *(float4*)&As[nxt][ar1][ac1] = a1v;
            *(float4*)&Bs[nxt][br0][bc0] = b0v;
            *(float4*)&Bs[nxt][br1][bc1] = b1v;
            __syncthreads();
            cur = nxt;
        }
    }
#pragma unroll
    for (int i = 0; i < 4; i++)
#pragma unroll
        for (int j = 0; j < 2; j++)
            wmma::store_matrix_sync(
                g_tmp + (long)(brow0 + wr * 64 + i * 16) * 256 + bcol0 + wc * 32 + j * 16,
                c[i][j], 256, wmma::mem_row_major);
}

// ---------------- GCN pull: warp per dst ----------------
__global__ void k_gcn_pull(const float* __restrict__ b, int outoff, int n, int g, int degoff) {
    int w = (blockIdx.x * blockDim.x + threadIdx.x) >> 5;
    int lane = threadIdx.x & 31;
    if (w >= n) return;
    int rb = g * NTOT;
    int r0 = g_rowg[rb + w], r1 = g_rowg[rb + w + 1];
    float dd = g_deg[degoff + w];
    const float4* hp = (const float4*)(g_tmp + (long)w * FDIM);
    float4 a0 = hp[lane];
    float4 a1 = hp[lane + 32];
    float sc = dd * dd;
    a0.x *= sc; a0.y *= sc; a0.z *= sc; a0.w *= sc;
    a1.x *= sc; a1.y *= sc; a1.z *= sc; a1.w *= sc;
    for (int j = r0; j < r1; j++) {
        int s = g_srt[j];
        float nm = g_deg[degoff + s] * dd;
        const float4* sp = (const float4*)(g_tmp + (long)s * FDIM);
        float4 v0 = sp[lane];
        float4 v1 = sp[lane + 32];
        a0.x += v0.x * nm; a0.y += v0.y * nm; a0.z += v0.z * nm; a0.w += v0.w * nm;
        a1.x += v1.x * nm; a1.y += v1.y * nm; a1.z += v1.z * nm; a1.w += v1.w * nm;
    }
    float4 b0 = *((const float4*)b + lane);
    float4 b1 = *((const float4*)b + lane + 32);
    a0.x += b0.x; a0.y += b0.y; a0.z += b0.z; a0.w += b0.w;
    a1.x += b1.x; a1.y += b1.y; a1.z += b1.z; a1.w += b1.w;
    float4* op = (float4*)(g_h + outoff + (long)w * FDIM);
    op[lane] = a0;
    op[lane + 32] = a1;
}

// ---------------- BN ----------------
__global__ void k_zero_stats() {
    g_csum[blockIdx.x][threadIdx.x] = 0.f;
    g_csq[blockIdx.x][threadIdx.x] = 0.f;
}
__global__ void k_colstats(int which, int off, int nrows, int slot) {
    const float* x = BUF(which) + off;
    int col = threadIdx.x;
    float s = 0.f, q = 0.f;
    for (int r = blockIdx.x; r < nrows; r += gridDim.x) {
        float v = x[r * FDIM + col];
        s += v;
        q += v * v;
    }
    atomicAdd(&g_csum[slot][col], s);
    atomicAdd(&g_csq[slot][col], q);
}
// all 4 head stats in one launch: grid = 4*256 blocks
__global__ void k_colstats4() {
    int grp = blockIdx.x >> 8;
    int blk = blockIdx.x & 255;
    const float* x;
    int nrows;
    switch (grp) {
        case 0: x = g_xb; nrows = NAB; break;
        case 1: x = g_xb + NAB * FDIM; nrows = NAG; break;
        case 2: x = g_h; nrows = NAB; break;
        default: x = g_h + NAB * FDIM; nrows = NAG; break;
    }
    int col = threadIdx.x;
    float s = 0.f, q = 0.f;
    for (int r = blk; r < nrows; r += 256) {
        float v = x[r * FDIM + col];
        s += v;
        q += v * v;
    }
    atomicAdd(&g_csum[grp][col], s);
    atomicAdd(&g_csq[grp][col], q);
}
__global__ void k_bn_relu(int which, int off, int nrows, int slot,
                          const float* __restrict__ g, const float* __restrict__ be) {
    float* x = BUF(which) + off;
    int idx = blockIdx.x * blockDim.x + threadIdx.x;
    if (idx < nrows * 64) {
        int f = (idx & 63) << 2;
        float n = (float)nrows;
        float4 v = *((float4*)x + idx);
        float* pv = &v.x;
#pragma unroll
        for (int j = 0; j < 4; j++) {
            float mu = g_csum[slot][f + j] / n;
            float var = g_csq[slot][f + j] / n - mu * mu;
            float o = (pv[j] - mu) * rsqrtf(var + EPSV) * g[f + j] + be[f + j];
            pv[j] = o > 0.f ? o : 0.f;
        }
        *((float4*)x + idx) = v;
    }
}

// ---------------- GAT ----------------
__global__ void k_dots(const float* __restrict__ a_s, const float* __restrict__ a_d) {
    int w = (blockIdx.x * blockDim.x + threadIdx.x) >> 5;
    int lane = threadIdx.x & 31;
    if (w >= NTOT) return;
    const float4* hp = (const float4*)(g_tmp + (long)w * FDIM);
    const float4* ap = (const float4*)a_s;
    const float4* dp = (const float4*)a_d;
    float s = 0.f, d = 0.f;
#pragma unroll
    for (int c = 0; c < 2; c++) {
        float4 hv = hp[lane + c * 32];
        float4 av = ap[lane + c * 32];
        float4 dv = dp[lane + c * 32];
        s += hv.x * av.x + hv.y * av.y + hv.z * av.z + hv.w * av.w;
        d += hv.x * dv.x + hv.y * dv.y + hv.z * dv.z + hv.w * dv.w;
    }
#pragma unroll
    for (int o = 16; o; o >>= 1) {
        s += __shfl_xor_sync(0xFFFFFFFFu, s, o);
        d += __shfl_xor_sync(0xFFFFFFFFu, d, o);
    }
    if (lane == 0) {
        g_es[w] = s;
        g_ed[w] = d;
    }
}
__global__ void k_gat_pull(int accwhich, const float* __restrict__ b, int dorelu) {
    int w = (blockIdx.x * blockDim.x + threadIdx.x) >> 5;
    int lane = threadIdx.x & 31;
    if (w >= NTOT) return;
    int rb = 2 * NTOT;
    int r0 = g_rowg[rb + w], r1 = g_rowg[rb + w + 1];
    float edd = g_ed[w];
    float eself = lrelu(g_es[w] + edd);
    float m = eself;
    for (int j = r0 + lane; j < r1; j += 32) {
        m = fmaxf(m, lrelu(g_es[g_srt[j]] + edd));
    }
#pragma unroll
    for (int o = 16; o; o >>= 1) m = fmaxf(m, __shfl_xor_sync(0xFFFFFFFFu, m, o));
    float exs = __expf(eself - m);
    float ssum = exs;
    const float4* hp = (const float4*)(g_tmp + (long)w * FDIM);
    float4 a0 = hp[lane];
    float4 a1 = hp[lane + 32];
    a0.x *= exs; a0.y *= exs; a0.z *= exs; a0.w *= exs;
    a1.x *= exs; a1.y *= exs; a1.z *= exs; a1.w *= exs;
    for (int j = r0; j < r1; j++) {
        int s = g_srt[j];
        float ex = __expf(lrelu(g_es[s] + edd) - m);
        ssum += ex;
        const float4* sp = (const float4*)(g_tmp + (long)s * FDIM);
        float4 v0 = sp[lane];
        float4 v1 = sp[lane + 32];
        a0.x += v0.x * ex; a0.y += v0.y * ex; a0.z += v0.z * ex; a0.w += v0.w * ex;
        a1.x += v1.x * ex; a1.y += v1.y * ex; a1.z += v1.z * ex; a1.w += v1.w * ex;
    }
    float inv = 1.0f / ssum;
    float4 b0 = *((const float4*)b + lane);
    float4 b1 = *((const float4*)b + lane + 32);
    a0.x = a0.x * inv + b0.x; a0.y = a0.y * inv + b0.y;
    a0.z = a0.z * inv + b0.z; a0.w = a0.w * inv + b0.w;
    a1.x = a1.x * inv + b1.x; a1.y = a1.y * inv + b1.y;
    a1.z = a1.z * inv + b1.z; a1.w = a1.w * inv + b1.w;
    if (dorelu) {
        a0.x = fmaxf(a0.x, 0.f); a0.y = fmaxf(a0.y, 0.f);
        a0.z = fmaxf(a0.z, 0.f); a0.w = fmaxf(a0.w, 0.f);
        a1.x = fmaxf(a1.x, 0.f); a1.y = fmaxf(a1.y, 0.f);
        a1.z = fmaxf(a1.z, 0.f); a1.w = fmaxf(a1.w, 0.f);
    }
    float4* op = (float4*)(BUF(accwhich) + (long)w * FDIM);
    op[lane] = a0;
    op[lane + 32] = a1;
}

// ---------------- final heads ----------------
__global__ void k_head(int xoff, int hoff, int slot_x, int slot_h,
                       const float* __restrict__ g, const float* __restrict__ be,
                       const float* __restrict__ W, const float* __restrict__ b,
                       float* __restrict__ out, int nrows) {
    __shared__ float red[8];
    const float* xpart = g_xb + xoff;
    const float* hpart = g_h + hoff;
    int row = blockIdx.x;
    int t = threadIdx.x;
    int lane = t & 31, wid = t >> 5;
    float n = (float)nrows;
    float mu1 = g_csum[slot_x][t] / n;
    float var1 = g_csq[slot_x][t] / n - mu1 * mu1;
    float v1 = (xpart[row * FDIM + t] - mu1) * rsqrtf(var1 + EPSV) * g[t] + be[t];
    v1 = v1 > 0.f ? v1 : 0.f;
    float mu2 = g_csum[slot_h][t] / n;
    float var2 = g_csq[slot_h][t] / n - mu2 * mu2;
    float v2 = (hpart[row * FDIM + t] - mu2) * rsqrtf(var2 + EPSV) * g[FDIM + t] + be[FDIM + t];
    v2 = v2 > 0.f ? v2 : 0.f;
    float p = v1 * W[t] + v2 * W[FDIM + t];
#pragma unroll
    for (int o = 16; o; o >>= 1) p += __shfl_xor_sync(0xFFFFFFFFu, p, o);
    if (lane == 0) red[wid] = p;
    __syncthreads();
    if (t == 0) {
        float acc = red[0];
#pragma unroll
        for (int i = 1; i < 8; i++) acc += red[i];
        out[row] = acc + b[0];
    }
}

// ---------------- host orchestration (launches ONLY) ----------------
static void run_gcn(const float* x, const float* W, const float* b, int n, int g,
                    int degoff, const float* gam, const float* be, int outoff) {
    dim3 gg(2, (n + 127) / 128);
    k_gemm<<<gg, 256>>>(x, -1, W, n);
    k_gcn_pull<<<(n + 7) / 8, 256>>>(b, outoff, n, g, degoff);
    k_zero_stats<<<1, 256>>>();
    k_colstats<<<256, 256>>>(0, outoff, n, 0);
    k_bn_relu<<<(n * 64 + 255) / 256, 256>>>(0, outoff, n, 0, gam, be);
}

static void run_gat(int inwhich, const float* W, const float* a_s, const float* a_d,
                    const float* b, int accwhich, int dorelu) {
    dim3 gg(2, (NTOT + 127) / 128);
    k_gemm<<<gg, 256>>>(nullptr, inwhich, W, NTOT);
    k_dots<<<(NTOT + 7) / 8, 256>>>(a_s, a_d);
    k_gat_pull<<<(NTOT + 7) / 8, 256>>>(accwhich, b, dorelu);
}

extern "C" void kernel_launch(void* const* d_in, const int* in_sizes, int n_in, void* d_out,
                              int out_size) {
    const float* x_ab = (const float*)d_in[0];
    const float* x_ag = (const float*)d_in[1];
    const float* W_gcn = (const float*)d_in[2];
    const float* b_gcn = (const float*)d_in[3];
    const float* g1 = (const float*)d_in[4];
    const float* be1 = (const float*)d_in[5];
    const float* W_aggcn = (const float*)d_in[6];
    const float* b_aggcn = (const float*)d_in[7];
    const float* ag_g1 = (const float*)d_in[8];
    const float* ag_be1 = (const float*)d_in[9];
    const float* W_gat = (const float*)d_in[10];
    const float* a_src = (const float*)d_in[11];
    const float* a_dst = (const float*)d_in[12];
    const float* b_gat = (const float*)d_in[13];
    const float* W_gat2 = (const float*)d_in[14];
    const float* a_src2 = (const float*)d_in[15];
    const float* a_dst2 = (const float*)d_in[16];
    const float* b_gat2 = (const float*)d_in[17];
    const float* ag_g2 = (const float*)d_in[18];
    const float* ag_be2 = (const float*)d_in[19];
    const float* W_agfc = (const float*)d_in[20];
    const float* b_agfc = (const float*)d_in[21];
    const float* g2 = (const float*)d_in[22];
    const float* be2 = (const float*)d_in[23];
    const float* W_fc = (const float*)d_in[24];
    const float* b_fc = (const float*)d_in[25];
    const int* e_ab = (const int*)d_in[26];
    const int* e_ag = (const int*)d_in[27];
    const int* e_d = (const int*)d_in[28];
    float* out = (float*)d_out;

    // batched CSR build (all 3 graphs, global prefix)
    k_zero_csr<<<(CSRN + 255) / 256, 256>>>();
    k_hist_all<<<(ETOT + 255) / 256, 256>>>(e_ab + EAB, e_ag + EAG, e_d + ED);
    k_dinv_all<<<(NTOT + 255) / 256, 256>>>();
    k_scan1<<<SCAN_BLOCKS, 1024>>>();
    k_scan2<<<1, 128>>>();
    k_scan3<<<SCAN_BLOCKS, 1024>>>();
    k_zero_csr<<<(CSRN + 255) / 256, 256>>>();
    k_fill_all<<<(ETOT + 255) / 256, 256>>>(e_ab, e_ag, e_d);

    // GCN on AB graph -> g_h rows [0, NAB)
    run_gcn(x_ab, W_gcn, b_gcn, NAB, 0, 0, g1, be1, 0);
    // GCN on AG graph -> g_h rows [NAB, NTOT)
    run_gcn(x_ag, W_aggcn, b_aggcn, NAG, 1, NAB, ag_g1, ag_be1, NAB * FDIM);

    // GAT layer 1: g_h(0) -> g_xa(1), relu
    run_gat(0, W_gat, a_src, a_dst, b_gat, 1, 1);
    // GAT layer 2: g_xa(1) -> g_xb(2), no relu
    run_gat(1, W_gat2, a_src2, a_dst2, b_gat2, 2, 0);

    // head stats: x1, x2, h_ab, h_ag — one launch
    k_zero_stats<<<4, 256>>>();
    k_colstats4<<<1024, 256>>>();

    // out_ab then out_ag
    k_head<<<NAB, 256>>>(0, 0, 0, 2, g2, be2, W_fc, b_fc, out, NAB);
    k_head<<<NAG, 256>>>(NAB * FDIM, NAB * FDIM, 1, 3, ag_g2, ag_be2, W_agfc, b_agfc,
                         out + NAB, NAG);
}

// round 11
// speedup vs baseline: 2.9364x; 1.1055x over previous
#include <cuda_runtime.h>
#include <mma.h>
using namespace nvcuda;

#define NAB 20000
#define NAG 20000
#define NTOT 40000
#define FDIM 256
#define EAB 320000
#define EAG 320000
#define ED 640000
#define ETOT (EAB + EAG + ED)
#define EPSV 1e-5f
#define MPAD 40064  // 313*128, GEMM tile padding
#define CSRN (3 * NTOT)
#define SCAN_BLOCKS ((CSRN + 1023) / 1024)
#define ALD 20   // padded As leading dim
#define BLD 132  // padded Bs leading dim

// ---------------- scratch (device globals; no allocs) ----------------
__device__ float g_h[NTOT * FDIM];    // 0
__device__ float g_xa[NTOT * FDIM];   // 1
__device__ float g_xb[NTOT * FDIM];   // 2
__device__ float g_tmp[MPAD * FDIM];  // 3 (padded for full-tile GEMM stores)
__device__ float g_deg[NTOT];
__device__ float g_es[NTOT];
__device__ float g_ed[NTOT];
__device__ float g_csum[4][FDIM];
__device__ float g_csq[4][FDIM];
// CSR: 3 graphs concatenated; global prefix in g_rowg; g_cnt doubles as fill cursor
__device__ int g_cnt[CSRN];
__device__ int g_rowg[CSRN + 1];
__device__ int g_bsum[SCAN_BLOCKS];
__device__ int g_srt[ETOT];

__device__ __forceinline__ float* BUF(int which) {
    switch (which) {
        case 0: return g_h;
        case 1: return g_xa;
        case 2: return g_xb;
        default: return g_tmp;
    }
}

__device__ __forceinline__ float lrelu(float x) { return x > 0.f ? x : 0.2f * x; }

// ---------------- batched CSR build ----------------
__global__ void k_zero_csr() {
    int i = blockIdx.x * blockDim.x + threadIdx.x;
    if (i < CSRN) g_cnt[i] = 0;
}
__global__ void k_hist_all(const int* __restrict__ dab, const int* __restrict__ dag,
                           const int* __restrict__ dd) {
    int e = blockIdx.x * blockDim.x + threadIdx.x;
    if (e < EAB) atomicAdd(&g_cnt[0 * NTOT + dab[e]], 1);
    else if (e < EAB + EAG) atomicAdd(&g_cnt[1 * NTOT + dag[e - EAB]], 1);
    else if (e < ETOT) atomicAdd(&g_cnt[2 * NTOT + dd[e - EAB - EAG]], 1);
}
// scan part 1 — per-block exclusive scan + block sums; also computes dinv
__global__ void k_scan1() {
    __shared__ int wsum[32];
    int gi = blockIdx.x * 1024 + threadIdx.x;
    int v = (gi < CSRN) ? g_cnt[gi] : 0;
    // fused dinv: graph0 nodes [0,NAB), graph1 nodes [NTOT, NTOT+NAG)
    if (gi < NAB) g_deg[gi] = rsqrtf((float)(v + 1));
    else if (gi >= NTOT && gi < NTOT + NAG) g_deg[NAB + gi - NTOT] = rsqrtf((float)(v + 1));
    int lane = threadIdx.x & 31, wid = threadIdx.x >> 5;
    int inc = v;
#pragma unroll
    for (int o = 1; o < 32; o <<= 1) {
        int u = __shfl_up_sync(0xFFFFFFFFu, inc, o);
        if (lane >= o) inc += u;
    }
    if (lane == 31) wsum[wid] = inc;
    __syncthreads();
    if (wid == 0) {
        int w = wsum[lane];
#pragma unroll
        for (int o = 1; o < 32; o <<= 1) {
            int u = __shfl_up_sync(0xFFFFFFFFu, w, o);
            if (lane >= o) w += u;
        }
        wsum[lane] = w;
    }
    __syncthreads();
    int ex = inc - v + (wid ? wsum[wid - 1] : 0);
    if (gi < CSRN) g_rowg[gi] = ex;
    if (threadIdx.x == 1023) g_bsum[blockIdx.x] = ex + v;
}
// scan part 2 — exclusive scan of block sums
__global__ void k_scan2() {
    __shared__ int ws[4];
    int t = threadIdx.x;
    int lane = t & 31, wid = t >> 5;
    int v = (t < SCAN_BLOCKS) ? g_bsum[t] : 0;
    int inc = v;
#pragma unroll
    for (int o = 1; o < 32; o <<= 1) {
        int u = __shfl_up_sync(0xFFFFFFFFu, inc, o);
        if (lane >= o) inc += u;
    }
    if (lane == 31) ws[wid] = inc;
    __syncthreads();
    int add = 0;
    for (int i = 0; i < wid; i++) add += ws[i];
    if (t < SCAN_BLOCKS) g_bsum[t] = inc - v + add;
}
// scan part 3 — add block offsets; init fill cursor
__global__ void k_scan3() {
    int gi = blockIdx.x * 1024 + threadIdx.x;
    if (gi < CSRN) {
        int r = g_rowg[gi] + g_bsum[blockIdx.x];
        g_rowg[gi] = r;
        g_cnt[gi] = r;  // cursor for fill
    }
    if (gi == 0) g_rowg[CSRN] = ETOT;
}
__global__ void k_fill_all(const int* __restrict__ eab, const int* __restrict__ eag,
                           const int* __restrict__ ed) {
    int e = blockIdx.x * blockDim.x + threadIdx.x;
    int g, le;
    const int* src;
    const int* dst;
    if (e < EAB) { g = 0; le = e; src = eab; dst = eab + EAB; }
    else if (e < EAB + EAG) { g = 1; le = e - EAB; src = eag; dst = eag + EAG; }
    else if (e < ETOT) { g = 2; le = e - EAB - EAG; src = ed; dst = ed + ED; }
    else return;
    int d = dst[le];
    int pos = atomicAdd(&g_cnt[g * NTOT + d], 1);
    g_srt[pos] = src[le];
}

// ---------------- TF32 wmma GEMM: g_tmp[M,256] = A[M,256] @ B[256,256] ----------------
// cvt-to-tf32 at SMEM store; padded SMEM to avoid bank conflicts
__global__ void __launch_bounds__(256, 2)
k_gemm(const float* __restrict__ Aext, int awhich, const float* __restrict__ B, int M) {
    const float* A = (awhich < 0) ? Aext : BUF(awhich);
    __shared__ alignas(16) float As[2][128][ALD];
    __shared__ alignas(16) float Bs[2][16][BLD];
    int t = threadIdx.x;
    int wid = t >> 5;
    int wr = wid >> 2;  // 0..1
    int wc = wid & 3;   // 0..3
    int brow0 = blockIdx.y * 128;
    int bcol0 = blockIdx.x * 128;

    wmma::fragment<wmma::accumulator, 16, 16, 8, float> c[4][2];
#pragma unroll
    for (int i = 0; i < 4; i++)
#pragma unroll
        for (int j = 0; j < 2; j++) wmma::fill_fragment(c[i][j], 0.0f);

    int af0 = t * 2, af1 = t * 2 + 1;
    int ar0 = af0 >> 2, ac0 = (af0 & 3) << 2;
    int ar1 = af1 >> 2, ac1 = (af1 & 3) << 2;
    int br0 = af0 >> 5, bc0 = (af0 & 31) << 2;
    int br1 = af1 >> 5, bc1 = (af1 & 31) << 2;

#define CVT4(v)                                  \
    do {                                         \
        (v).x = wmma::__float_to_tf32((v).x);    \
        (v).y = wmma::__float_to_tf32((v).y);    \
        (v).z = wmma::__float_to_tf32((v).z);    \
        (v).w = wmma::__float_to_tf32((v).w);    \
    } while (0)

    // prologue: tile 0
    {
        float4 z = make_float4(0.f, 0.f, 0.f, 0.f);
        float4 a0v = (brow0 + ar0 < M) ? *(const float4*)(A + (brow0 + ar0) * 256 + ac0) : z;
        float4 a1v = (brow0 + ar1 < M) ? *(const float4*)(A + (brow0 + ar1) * 256 + ac1) : z;
        float4 b0v = *(const float4*)(B + br0 * 256 + bcol0 + bc0);
        float4 b1v = *(const float4*)(B + br1 * 256 + bcol0 + bc1);
        CVT4(a0v); CVT4(a1v); CVT4(b0v); CVT4(b1v);
        *(float4*)&As[0][ar0][ac0] = a0v;
        *(float4*)&As[0][ar1][ac1] = a1v;
        *(float4*)&Bs[0][br0][bc0] = b0v;
        *(float4*)&Bs[0][br1][bc1] = b1v;
    }
    __syncthreads();
    int cur = 0;
    for (int k0 = 16; k0 <= 256; k0 += 16) {
        float4 a0v, a1v, b0v, b1v;
        if (k0 < 256) {
            float4 z = make_float4(0.f, 0.f, 0.f, 0.f);
            a0v = (brow0 + ar0 < M) ? *(const float4*)(A + (brow0 + ar0) * 256 + k0 + ac0) : z;
            a1v = (brow0 + ar1 < M) ? *(const float4*)(A + (brow0 + ar1) * 256 + k0 + ac1) : z;
            b0v = *(const float4*)(B + (k0 + br0) * 256 + bcol0 + bc0);
            b1v = *(const float4*)(B + (k0 + br1) * 256 + bcol0 + bc1);
        }
#pragma unroll
        for (int kk = 0; kk < 16; kk += 8) {
            wmma::fragment<wmma::matrix_a, 16, 16, 8, wmma::precision::tf32, wmma::row_major> a[4];
            wmma::fragment<wmma::matrix_b, 16, 16, 8, wmma::precision::tf32, wmma::row_major> b[2];
#pragma unroll
            for (int i = 0; i < 4; i++)
                wmma::load_matrix_sync(a[i], &As[cur][wr * 64 + i * 16][kk], ALD);
#pragma unroll
            for (int j = 0; j < 2; j++)
                wmma::load_matrix_sync(b[j], &Bs[cur][kk][wc * 32 + j * 16], BLD);
#pragma unroll
            for (int i = 0; i < 4; i++)
#pragma unroll
                for (int j = 0; j < 2; j++) wmma::mma_sync(c[i][j], a[i], b[j], c[i][j]);
        }
        if (k0 < 256) {
            int nxt = cur ^ 1;
            CVT4(a0v); CVT4(a1v); CVT4(b0v); CVT4(b1v);
            *(float4*)&As[nxt][ar0][ac0] = a0v;
            *(float4*)&As[nxt][ar1][ac1] = a1v;
            *(float4*)&Bs[nxt][br0][bc0] = b0v;
            *(float4*)&Bs[nxt][br1][bc1] = b1v;
            __syncthreads();
            cur = nxt;
        }
    }
#pragma unroll
    for (int i = 0; i < 4; i++)
#pragma unroll
        for (int j = 0; j < 2; j++)
            wmma::store_matrix_sync(
                g_tmp + (long)(brow0 + wr * 64 + i * 16) * 256 + bcol0 + wc * 32 + j * 16,
                c[i][j], 256, wmma::mem_row_major);
#undef CVT4
}

// ---------------- GCN pull: warp per dst ----------------
__global__ void k_gcn_pull(const float* __restrict__ b, int outoff, int n, int g, int degoff) {
    int w = (blockIdx.x * blockDim.x + threadIdx.x) >> 5;
    int lane = threadIdx.x & 31;
    if (w >= n) return;
    int rb = g * NTOT;
    int r0 = g_rowg[rb + w], r1 = g_rowg[rb + w + 1];
    float dd = g_deg[degoff + w];
    const float4* hp = (const float4*)(g_tmp + (long)w * FDIM);
    float4 a0 = hp[lane];
    float4 a1 = hp[lane + 32];
    float sc = dd * dd;
    a0.x *= sc; a0.y *= sc; a0.z *= sc; a0.w *= sc;
    a1.x *= sc; a1.y *= sc; a1.z *= sc; a1.w *= sc;
    for (int j = r0; j < r1; j++) {
        int s = g_srt[j];
        float nm = g_deg[degoff + s] * dd;
        const float4* sp = (const float4*)(g_tmp + (long)s * FDIM);
        float4 v0 = sp[lane];
        float4 v1 = sp[lane + 32];
        a0.x += v0.x * nm; a0.y += v0.y * nm; a0.z += v0.z * nm; a0.w += v0.w * nm;
        a1.x += v1.x * nm; a1.y += v1.y * nm; a1.z += v1.z * nm; a1.w += v1.w * nm;
    }
    float4 b0 = *((const float4*)b + lane);
    float4 b1 = *((const float4*)b + lane + 32);
    a0.x += b0.x; a0.y += b0.y; a0.z += b0.z; a0.w += b0.w;
    a1.x += b1.x; a1.y += b1.y; a1.z += b1.z; a1.w += b1.w;
    float4* op = (float4*)(g_h + outoff + (long)w * FDIM);
    op[lane] = a0;
    op[lane + 32] = a1;
}

// ---------------- BN ----------------
__global__ void k_zero_stats() {
    g_csum[blockIdx.x][threadIdx.x] = 0.f;
    g_csq[blockIdx.x][threadIdx.x] = 0.f;
}
__global__ void k_colstats(int which, int off, int nrows, int slot) {
    const float* x = BUF(which) + off;
    int col = threadIdx.x;
    float s = 0.f, q = 0.f;
    for (int r = blockIdx.x; r < nrows; r += gridDim.x) {
        float v = x[r * FDIM + col];
        s += v;
        q += v * v;
    }
    atomicAdd(&g_csum[slot][col], s);
    atomicAdd(&g_csq[slot][col], q);
}
__global__ void k_colstats4() {
    int grp = blockIdx.x >> 8;
    int blk = blockIdx.x & 255;
    const float* x;
    int nrows;
    switch (grp) {
        case 0: x = g_xb; nrows = NAB; break;
        case 1: x = g_xb + NAB * FDIM; nrows = NAG; break;
        case 2: x = g_h; nrows = NAB; break;
        default: x = g_h + NAB * FDIM; nrows = NAG; break;
    }
    int col = threadIdx.x;
    float s = 0.f, q = 0.f;
    for (int r = blk; r < nrows; r += 256) {
        float v = x[r * FDIM + col];
        s += v;
        q += v * v;
    }
    atomicAdd(&g_csum[grp][col], s);
    atomicAdd(&g_csq[grp][col], q);
}
__global__ void k_bn_relu(int which, int off, int nrows, int slot,
                          const float* __restrict__ g, const float* __restrict__ be) {
    float* x = BUF(which) + off;
    int idx = blockIdx.x * blockDim.x + threadIdx.x;
    if (idx < nrows * 64) {
        int f = (idx & 63) << 2;
        float n = (float)nrows;
        float4 v = *((float4*)x + idx);
        float* pv = &v.x;
#pragma unroll
        for (int j = 0; j < 4; j++) {
            float mu = g_csum[slot][f + j] / n;
            float var = g_csq[slot][f + j] / n - mu * mu;
            float o = (pv[j] - mu) * rsqrtf(var + EPSV) * g[f + j] + be[f + j];
            pv[j] = o > 0.f ? o : 0.f;
        }
        *((float4*)x + idx) = v;
    }
}

// ---------------- GAT ----------------
__global__ void k_dots(const float* __restrict__ a_s, const float* __restrict__ a_d) {
    int w = (blockIdx.x * blockDim.x + threadIdx.x) >> 5;
    int lane = threadIdx.x & 31;
    if (w >= NTOT) return;
    const float4* hp = (const float4*)(g_tmp + (long)w * FDIM);
    const float4* ap = (const float4*)a_s;
    const float4* dp = (const float4*)a_d;
    float s = 0.f, d = 0.f;
#pragma unroll
    for (int c = 0; c < 2; c++) {
        float4 hv = hp[lane + c * 32];
        float4 av = ap[lane + c * 32];
        float4 dv = dp[lane + c * 32];
        s += hv.x * av.x + hv.y * av.y + hv.z * av.z + hv.w * av.w;
        d += hv.x * dv.x + hv.y * dv.y + hv.z * dv.z + hv.w * dv.w;
    }
#pragma unroll
    for (int o = 16; o; o >>= 1) {
        s += __shfl_xor_sync(0xFFFFFFFFu, s, o);
        d += __shfl_xor_sync(0xFFFFFFFFu, d, o);
    }
    if (lane == 0) {
        g_es[w] = s;
        g_ed[w] = d;
    }
}
__global__ void k_gat_pull(int accwhich, const float* __restrict__ b, int dorelu) {
    int w = (blockIdx.x * blockDim.x + threadIdx.x) >> 5;
    int lane = threadIdx.x & 31;
    if (w >= NTOT) return;
    int rb = 2 * NTOT;
    int r0 = g_rowg[rb + w], r1 = g_rowg[rb + w + 1];
    float edd = g_ed[w];
    float eself = lrelu(g_es[w] + edd);
    float m = eself;
    for (int j = r0 + lane; j < r1; j += 32) {
        m = fmaxf(m, lrelu(g_es[g_srt[j]] + edd));
    }
#pragma unroll
    for (int o = 16; o; o >>= 1) m = fmaxf(m, __shfl_xor_sync(0xFFFFFFFFu, m, o));
    float exs = __expf(eself - m);
    float ssum = exs;
    const float4* hp = (const float4*)(g_tmp + (long)w * FDIM);
    float4 a0 = hp[lane];
    float4 a1 = hp[lane + 32];
    a0.x *= exs; a0.y *= exs; a0.z *= exs; a0.w *= exs;
    a1.x *= exs; a1.y *= exs; a1.z *= exs; a1.w *= exs;
    for (int j = r0; j < r1; j++) {
        int s = g_srt[j];
        float ex = __expf(lrelu(g_es[s] + edd) - m);
        ssum += ex;
        const float4* sp = (const float4*)(g_tmp + (long)s * FDIM);
        float4 v0 = sp[lane];
        float4 v1 = sp[lane + 32];
        a0.x += v0.x * ex; a0.y += v0.y * ex; a0.z += v0.z * ex; a0.w += v0.w * ex;
        a1.x += v1.x * ex; a1.y += v1.y * ex; a1.z += v1.z * ex; a1.w += v1.w * ex;
    }
    float inv = 1.0f / ssum;
    float4 b0 = *((const float4*)b + lane);
    float4 b1 = *((const float4*)b + lane + 32);
    a0.x = a0.x * inv + b0.x; a0.y = a0.y * inv + b0.y;
    a0.z = a0.z * inv + b0.z; a0.w = a0.w * inv + b0.w;
    a1.x = a1.x * inv + b1.x; a1.y = a1.y * inv + b1.y;
    a1.z = a1.z * inv + b1.z; a1.w = a1.w * inv + b1.w;
    if (dorelu) {
        a0.x = fmaxf(a0.x, 0.f); a0.y = fmaxf(a0.y, 0.f);
        a0.z = fmaxf(a0.z, 0.f); a0.w = fmaxf(a0.w, 0.f);
        a1.x = fmaxf(a1.x, 0.f); a1.y = fmaxf(a1.y, 0.f);
        a1.z = fmaxf(a1.z, 0.f); a1.w = fmaxf(a1.w, 0.f);
    }
    float4* op = (float4*)(BUF(accwhich) + (long)w * FDIM);
    op[lane] = a0;
    op[lane + 32] = a1;
}

// ---------------- final heads (both in one launch; grid = NTOT) ----------------
__global__ void k_head2(const float* __restrict__ g2, const float* __restrict__ be2,
                        const float* __restrict__ W_fc, const float* __restrict__ b_fc,
                        const float* __restrict__ ag_g2, const float* __restrict__ ag_be2,
                        const float* __restrict__ W_agfc, const float* __restrict__ b_agfc,
                        float* __restrict__ out) {
    __shared__ float red[8];
    int row = blockIdx.x;
    int t = threadIdx.x;
    int lane = t & 31, wid = t >> 5;
    const float *xpart, *hpart, *g, *be, *W, *b;
    int slot_x, slot_h, lrow;
    if (row < NAB) {
        lrow = row;
        xpart = g_xb; hpart = g_h;
        slot_x = 0; slot_h = 2;
        g = g2; be = be2; W = W_fc; b = b_fc;
    } else {
        lrow = row - NAB;
        xpart = g_xb + NAB * FDIM; hpart = g_h + NAB * FDIM;
        slot_x = 1; slot_h = 3;
        g = ag_g2; be = ag_be2; W = W_agfc; b = b_agfc;
    }
    float n = (float)NAB;  // NAB == NAG
    float mu1 = g_csum[slot_x][t] / n;
    float var1 = g_csq[slot_x][t] / n - mu1 * mu1;
    float v1 = (xpart[lrow * FDIM + t] - mu1) * rsqrtf(var1 + EPSV) * g[t] + be[t];
    v1 = v1 > 0.f ? v1 : 0.f;
    float mu2 = g_csum[slot_h][t] / n;
    float var2 = g_csq[slot_h][t] / n - mu2 * mu2;
    float v2 = (hpart[lrow * FDIM + t] - mu2) * rsqrtf(var2 + EPSV) * g[FDIM + t] + be[FDIM + t];
    v2 = v2 > 0.f ? v2 : 0.f;
    float p = v1 * W[t] + v2 * W[FDIM + t];
#pragma unroll
    for (int o = 16; o; o >>= 1) p += __shfl_xor_sync(0xFFFFFFFFu, p, o);
    if (lane == 0) red[wid] = p;
    __syncthreads();
    if (t == 0) {
        float acc = red[0];
#pragma unroll
        for (int i = 1; i < 8; i++) acc += red[i];
        out[row] = acc + b[0];
    }
}

// ---------------- host orchestration (launches ONLY) ----------------
static void run_gcn(const float* x, const float* W, const float* b, int n, int g,
                    int degoff, const float* gam, const float* be, int outoff) {
    dim3 gg(2, (n + 127) / 128);
    k_gemm<<<gg, 256>>>(x, -1, W, n);
    k_gcn_pull<<<(n + 7) / 8, 256>>>(b, outoff, n, g, degoff);
    k_zero_stats<<<1, 256>>>();
    k_colstats<<<256, 256>>>(0, outoff, n, 0);
    k_bn_relu<<<(n * 64 + 255) / 256, 256>>>(0, outoff, n, 0, gam, be);
}

static void run_gat(int inwhich, const float* W, const float* a_s, const float* a_d,
                    const float* b, int accwhich, int dorelu) {
    dim3 gg(2, (NTOT + 127) / 128);
    k_gemm<<<gg, 256>>>(nullptr, inwhich, W, NTOT);
    k_dots<<<(NTOT + 7) / 8, 256>>>(a_s, a_d);
    k_gat_pull<<<(NTOT + 7) / 8, 256>>>(accwhich, b, dorelu);
}

extern "C" void kernel_launch(void* const* d_in, const int* in_sizes, int n_in, void* d_out,
                              int out_size) {
    const float* x_ab = (const float*)d_in[0];
    const float* x_ag = (const float*)d_in[1];
    const float* W_gcn = (const float*)d_in[2];
    const float* b_gcn = (const float*)d_in[3];
    const float* g1 = (const float*)d_in[4];
    const float* be1 = (const float*)d_in[5];
    const float* W_aggcn = (const float*)d_in[6];
    const float* b_aggcn = (const float*)d_in[7];
    const float* ag_g1 = (const float*)d_in[8];
    const float* ag_be1 = (const float*)d_in[9];
    const float* W_gat = (const float*)d_in[10];
    const float* a_src = (const float*)d_in[11];
    const float* a_dst = (const float*)d_in[12];
    const float* b_gat = (const float*)d_in[13];
    const float* W_gat2 = (const float*)d_in[14];
    const float* a_src2 = (const float*)d_in[15];
    const float* a_dst2 = (const float*)d_in[16];
    const float* b_gat2 = (const float*)d_in[17];
    const float* ag_g2 = (const float*)d_in[18];
    const float* ag_be2 = (const float*)d_in[19];
    const float* W_agfc = (const float*)d_in[20];
    const float* b_agfc = (const float*)d_in[21];
    const float* g2 = (const float*)d_in[22];
    const float* be2 = (const float*)d_in[23];
    const float* W_fc = (const float*)d_in[24];
    const float* b_fc = (const float*)d_in[25];
    const int* e_ab = (const int*)d_in[26];
    const int* e_ag = (const int*)d_in[27];
    const int* e_d = (const int*)d_in[28];
    float* out = (float*)d_out;

    // batched CSR build (all 3 graphs, global prefix)
    k_zero_csr<<<(CSRN + 255) / 256, 256>>>();
    k_hist_all<<<(ETOT + 255) / 256, 256>>>(e_ab + EAB, e_ag + EAG, e_d + ED);
    k_scan1<<<SCAN_BLOCKS, 1024>>>();
    k_scan2<<<1, 128>>>();
    k_scan3<<<SCAN_BLOCKS, 1024>>>();
    k_fill_all<<<(ETOT + 255) / 256, 256>>>(e_ab, e_ag, e_d);

    // GCN on AB graph -> g_h rows [0, NAB)
    run_gcn(x_ab, W_gcn, b_gcn, NAB, 0, 0, g1, be1, 0);
    // GCN on AG graph -> g_h rows [NAB, NTOT)
    run_gcn(x_ag, W_aggcn, b_aggcn, NAG, 1, NAB, ag_g1, ag_be1, NAB * FDIM);

    // GAT layer 1: g_h(0) -> g_xa(1), relu
    run_gat(0, W_gat, a_src, a_dst, b_gat, 1, 1);
    // GAT layer 2: g_xa(1) -> g_xb(2), no relu
    run_gat(1, W_gat2, a_src2, a_dst2, b_gat2, 2, 0);

    // head stats: x1, x2, h_ab, h_ag — one launch
    k_zero_stats<<<4, 256>>>();
    k_colstats4<<<1024, 256>>>();

    // both heads in one launch
    k_head2<<<NTOT, 256>>>(g2, be2, W_fc, b_fc, ag_g2, ag_be2, W_agfc, b_agfc, out);
}

// round 12
// speedup vs baseline: 3.2493x; 1.1066x over previous
#include <cuda_runtime.h>
#include <mma.h>
using namespace nvcuda;

#define NAB 20000
#define NAG 20000
#define NTOT 40000
#define FDIM 256
#define EAB 320000
#define EAG 320000
#define ED 640000
#define ETOT (EAB + EAG + ED)
#define EPSV 1e-5f
#define MPAD 40192  // 2*157*128, room for dual-GEMM full-tile stores
#define CSRN (3 * NTOT)
#define SCAN_BLOCKS ((CSRN + 1023) / 1024)
#define ALD 20   // padded As leading dim
#define BLD 132  // padded Bs leading dim

// ---------------- scratch (device globals; no allocs) ----------------
__device__ float g_h[NTOT * FDIM];    // 0
__device__ float g_xa[NTOT * FDIM];   // 1
__device__ float g_xb[NTOT * FDIM];   // 2
__device__ float g_tmp[MPAD * FDIM];  // 3
__device__ float g_deg[NTOT];
__device__ float g_es[NTOT];
__device__ float g_ed[NTOT];
__device__ float g_csum[4][FDIM];
__device__ float g_csq[4][FDIM];
__device__ int g_cnt[CSRN];
__device__ int g_rowg[CSRN + 1];
__device__ int g_bsum[SCAN_BLOCKS];
__device__ int g_srt[ETOT];

__device__ __forceinline__ float* BUF(int which) {
    switch (which) {
        case 0: return g_h;
        case 1: return g_xa;
        case 2: return g_xb;
        default: return g_tmp;
    }
}

__device__ __forceinline__ float lrelu(float x) { return x > 0.f ? x : 0.2f * x; }

// ---------------- batched CSR build ----------------
__global__ void k_zero_csr() {
    int i = blockIdx.x * blockDim.x + threadIdx.x;
    if (i < CSRN) g_cnt[i] = 0;
}
__global__ void k_hist_all(const int* __restrict__ dab, const int* __restrict__ dag,
                           const int* __restrict__ dd) {
    int e = blockIdx.x * blockDim.x + threadIdx.x;
    if (e < EAB) atomicAdd(&g_cnt[0 * NTOT + dab[e]], 1);
    else if (e < EAB + EAG) atomicAdd(&g_cnt[1 * NTOT + dag[e - EAB]], 1);
    else if (e < ETOT) atomicAdd(&g_cnt[2 * NTOT + dd[e - EAB - EAG]], 1);
}
__global__ void k_scan1() {
    __shared__ int wsum[32];
    int gi = blockIdx.x * 1024 + threadIdx.x;
    int v = (gi < CSRN) ? g_cnt[gi] : 0;
    if (gi < NAB) g_deg[gi] = rsqrtf((float)(v + 1));
    else if (gi >= NTOT && gi < NTOT + NAG) g_deg[NAB + gi - NTOT] = rsqrtf((float)(v + 1));
    int lane = threadIdx.x & 31, wid = threadIdx.x >> 5;
    int inc = v;
#pragma unroll
    for (int o = 1; o < 32; o <<= 1) {
        int u = __shfl_up_sync(0xFFFFFFFFu, inc, o);
        if (lane >= o) inc += u;
    }
    if (lane == 31) wsum[wid] = inc;
    __syncthreads();
    if (wid == 0) {
        int w = wsum[lane];
#pragma unroll
        for (int o = 1; o < 32; o <<= 1) {
            int u = __shfl_up_sync(0xFFFFFFFFu, w, o);
            if (lane >= o) w += u;
        }
        wsum[lane] = w;
    }
    __syncthreads();
    int ex = inc - v + (wid ? wsum[wid - 1] : 0);
    if (gi < CSRN) g_rowg[gi] = ex;
    if (threadIdx.x == 1023) g_bsum[blockIdx.x] = ex + v;
}
__global__ void k_scan2() {
    __shared__ int ws[4];
    int t = threadIdx.x;
    int lane = t & 31, wid = t >> 5;
    int v = (t < SCAN_BLOCKS) ? g_bsum[t] : 0;
    int inc = v;
#pragma unroll
    for (int o = 1; o < 32; o <<= 1) {
        int u = __shfl_up_sync(0xFFFFFFFFu, inc, o);
        if (lane >= o) inc += u;
    }
    if (lane == 31) ws[wid] = inc;
    __syncthreads();
    int add = 0;
    for (int i = 0; i < wid; i++) add += ws[i];
    if (t < SCAN_BLOCKS) g_bsum[t] = inc - v + add;
}
__global__ void k_scan3() {
    int gi = blockIdx.x * 1024 + threadIdx.x;
    if (gi < CSRN) {
        int r = g_rowg[gi] + g_bsum[blockIdx.x];
        g_rowg[gi] = r;
        g_cnt[gi] = r;
    }
    if (gi == 0) g_rowg[CSRN] = ETOT;
}
__global__ void k_fill_all(const int* __restrict__ eab, const int* __restrict__ eag,
                           const int* __restrict__ ed) {
    int e = blockIdx.x * blockDim.x + threadIdx.x;
    int g, le;
    const int* src;
    const int* dst;
    if (e < EAB) { g = 0; le = e; src = eab; dst = eab + EAB; }
    else if (e < EAB + EAG) { g = 1; le = e - EAB; src = eag; dst = eag + EAG; }
    else if (e < ETOT) { g = 2; le = e - EAB - EAG; src = ed; dst = ed + ED; }
    else return;
    int d = dst[le];
    int pos = atomicAdd(&g_cnt[g * NTOT + d], 1);
    g_srt[pos] = src[le];
}

// ---------------- TF32 wmma GEMM core ----------------
// computes g_tmp[outrow0 + 0..M) = A[0..M) @ B; full-tile stores (MPAD padded)
__device__ __forceinline__ void gemm_body(const float* __restrict__ A,
                                          const float* __restrict__ B, int M, int outrow0,
                                          int by, int bx) {
    __shared__ alignas(16) float As[2][128][ALD];
    __shared__ alignas(16) float Bs[2][16][BLD];
    int t = threadIdx.x;
    int wid = t >> 5;
    int wr = wid >> 2;
    int wc = wid & 3;
    int brow0 = by * 128;
    int bcol0 = bx * 128;

    wmma::fragment<wmma::accumulator, 16, 16, 8, float> c[4][2];
#pragma unroll
    for (int i = 0; i < 4; i++)
#pragma unroll
        for (int j = 0; j < 2; j++) wmma::fill_fragment(c[i][j], 0.0f);

    int af0 = t * 2, af1 = t * 2 + 1;
    int ar0 = af0 >> 2, ac0 = (af0 & 3) << 2;
    int ar1 = af1 >> 2, ac1 = (af1 & 3) << 2;
    int br0 = af0 >> 5, bc0 = (af0 & 31) << 2;
    int br1 = af1 >> 5, bc1 = (af1 & 31) << 2;

#define CVT4(v)                                  \
    do {                                         \
        (v).x = wmma::__float_to_tf32((v).x);    \
        (v).y = wmma::__float_to_tf32((v).y);    \
        (v).z = wmma::__float_to_tf32((v).z);    \
        (v).w = wmma::__float_to_tf32((v).w);    \
    } while (0)

    {
        float4 z = make_float4(0.f, 0.f, 0.f, 0.f);
        float4 a0v = (brow0 + ar0 < M) ? *(const float4*)(A + (brow0 + ar0) * 256 + ac0) : z;
        float4 a1v = (brow0 + ar1 < M) ? *(const float4*)(A + (brow0 + ar1) * 256 + ac1) : z;
        float4 b0v = *(const float4*)(B + br0 * 256 + bcol0 + bc0);
        float4 b1v = *(const float4*)(B + br1 * 256 + bcol0 + bc1);
        CVT4(a0v); CVT4(a1v); CVT4(b0v); CVT4(b1v);
        *(float4*)&As[0][ar0][ac0] = a0v;
        *(float4*)&As[0][ar1][ac1] = a1v;
        *(float4*)&Bs[0][br0][bc0] = b0v;
        *(float4*)&Bs[0][br1][bc1] = b1v;
    }
    __syncthreads();
    int cur = 0;
    for (int k0 = 16; k0 <= 256; k0 += 16) {
        float4 a0v, a1v, b0v, b1v;
        if (k0 < 256) {
            float4 z = make_float4(0.f, 0.f, 0.f, 0.f);
            a0v = (brow0 + ar0 < M) ? *(const float4*)(A + (brow0 + ar0) * 256 + k0 + ac0) : z;
            a1v = (brow0 + ar1 < M) ? *(const float4*)(A + (brow0 + ar1) * 256 + k0 + ac1) : z;
            b0v = *(const float4*)(B + (k0 + br0) * 256 + bcol0 + bc0);
            b1v = *(const float4*)(B + (k0 + br1) * 256 + bcol0 + bc1);
        }
#pragma unroll
        for (int kk = 0; kk < 16; kk += 8) {
            wmma::fragment<wmma::matrix_a, 16, 16, 8, wmma::precision::tf32, wmma::row_major> a[4];
            wmma::fragment<wmma::matrix_b, 16, 16, 8, wmma::precision::tf32, wmma::row_major> b[2];
#pragma unroll
            for (int i = 0; i < 4; i++)
                wmma::load_matrix_sync(a[i], &As[cur][wr * 64 + i * 16][kk], ALD);
#pragma unroll
            for (int j = 0; j < 2; j++)
                wmma::load_matrix_sync(b[j], &Bs[cur][kk][wc * 32 + j * 16], BLD);
#pragma unroll
            for (int i = 0; i < 4; i++)
#pragma unroll
                for (int j = 0; j < 2; j++) wmma::mma_sync(c[i][j], a[i], b[j], c[i][j]);
        }
        if (k0 < 256) {
            int nxt = cur ^ 1;
            CVT4(a0v); CVT4(a1v); CVT4(b0v); CVT4(b1v);
            *(float4*)&As[nxt][ar0][ac0] = a0v;
            *(float4*)&As[nxt][ar1][ac1] = a1v;
            *(float4*)&Bs[nxt][br0][bc0] = b0v;
            *(float4*)&Bs[nxt][br1][bc1] = b1v;
            __syncthreads();
            cur = nxt;
        }
    }
#pragma unroll
    for (int i = 0; i < 4; i++)
#pragma unroll
        for (int j = 0; j < 2; j++)
            wmma::store_matrix_sync(
                g_tmp + (long)(outrow0 + brow0 + wr * 64 + i * 16) * 256 + bcol0 + wc * 32 +
                    j * 16,
                c[i][j], 256, wmma::mem_row_major);
#undef CVT4
}

// single GEMM: g_tmp = A @ B
__global__ void __launch_bounds__(256, 2)
k_gemm(const float* __restrict__ Aext, int awhich, const float* __restrict__ B, int M) {
    const float* A = (awhich < 0) ? Aext : BUF(awhich);
    gemm_body(A, B, M, 0, blockIdx.y, blockIdx.x);
}
// dual GCN GEMM: z=0 -> g_tmp[0..] = x_ab@W_gcn ; z=1 -> g_tmp[NAB..] = x_ag@W_aggcn
__global__ void __launch_bounds__(256, 2)
k_gemm2(const float* __restrict__ x_ab, const float* __restrict__ W_ab,
        const float* __restrict__ x_ag, const float* __restrict__ W_ag) {
    if (blockIdx.z == 0) gemm_body(x_ab, W_ab, NAB, 0, blockIdx.y, blockIdx.x);
    else gemm_body(x_ag, W_ag, NAG, NAB, blockIdx.y, blockIdx.x);
}

// ---------------- merged GCN pull: warp per dst over both graphs ----------------
__global__ void k_gcn_pull2(const float* __restrict__ b_ab, const float* __restrict__ b_ag) {
    int w = (blockIdx.x * blockDim.x + threadIdx.x) >> 5;
    int lane = threadIdx.x & 31;
    if (w >= NTOT) return;
    int g, local, tmprow;
    const float* b;
    if (w < NAB) { g = 0; local = w; tmprow = 0; b = b_ab; }
    else { g = 1; local = w - NAB; tmprow = NAB; b = b_ag; }
    int rb = g * NTOT;
    int r0 = g_rowg[rb + local], r1 = g_rowg[rb + local + 1];
    float dd = g_deg[w];
    const float4* hp = (const float4*)(g_tmp + (long)(tmprow + local) * FDIM);
    float4 a0 = hp[lane];
    float4 a1 = hp[lane + 32];
    float sc = dd * dd;
    a0.x *= sc; a0.y *= sc; a0.z *= sc; a0.w *= sc;
    a1.x *= sc; a1.y *= sc; a1.z *= sc; a1.w *= sc;
    int degbase = (g == 0) ? 0 : NAB;
    for (int j = r0; j < r1; j++) {
        int s = g_srt[j];
        float nm = g_deg[degbase + s] * dd;
        const float4* sp = (const float4*)(g_tmp + (long)(tmprow + s) * FDIM);
        float4 v0 = sp[lane];
        float4 v1 = sp[lane + 32];
        a0.x += v0.x * nm; a0.y += v0.y * nm; a0.z += v0.z * nm; a0.w += v0.w * nm;
        a1.x += v1.x * nm; a1.y += v1.y * nm; a1.z += v1.z * nm; a1.w += v1.w * nm;
    }
    float4 b0 = *((const float4*)b + lane);
    float4 b1 = *((const float4*)b + lane + 32);
    a0.x += b0.x; a0.y += b0.y; a0.z += b0.z; a0.w += b0.w;
    a1.x += b1.x; a1.y += b1.y; a1.z += b1.z; a1.w += b1.w;
    float4* op = (float4*)(g_h + (long)w * FDIM);
    op[lane] = a0;
    op[lane + 32] = a1;
}

// ---------------- BN ----------------
__global__ void k_zero_stats() {
    g_csum[blockIdx.x][threadIdx.x] = 0.f;
    g_csq[blockIdx.x][threadIdx.x] = 0.f;
}
// GCN stats: slot0 = g_h rows [0,NAB), slot1 = g_h rows [NAB,NTOT)
__global__ void k_colstats2() {
    int grp = blockIdx.x >> 8;
    int blk = blockIdx.x & 255;
    const float* x = grp ? (g_h + NAB * FDIM) : g_h;
    int nrows = grp ? NAG : NAB;
    int col = threadIdx.x;
    float s = 0.f, q = 0.f;
    for (int r = blk; r < nrows; r += 256) {
        float v = x[r * FDIM + col];
        s += v;
        q += v * v;
    }
    atomicAdd(&g_csum[grp][col], s);
    atomicAdd(&g_csq[grp][col], q);
}
// merged bn_relu over g_h, slot by row
__global__ void k_bn_relu2(const float* __restrict__ g_ab, const float* __restrict__ be_ab,
                           const float* __restrict__ g_ag, const float* __restrict__ be_ag) {
    int idx = blockIdx.x * blockDim.x + threadIdx.x;
    if (idx >= NTOT * 64) return;
    int row = idx >> 6;
    int slot = (row < NAB) ? 0 : 1;
    float n = (float)(slot ? NAG : NAB);
    const float* g = slot ? g_ag : g_ab;
    const float* be = slot ? be_ag : be_ab;
    int f = (idx & 63) << 2;
    float4 v = *((float4*)g_h + idx);
    float* pv = &v.x;
#pragma unroll
    for (int j = 0; j < 4; j++) {
        float mu = g_csum[slot][f + j] / n;
        float var = g_csq[slot][f + j] / n - mu * mu;
        float o = (pv[j] - mu) * rsqrtf(var + EPSV) * g[f + j] + be[f + j];
        pv[j] = o > 0.f ? o : 0.f;
    }
    *((float4*)g_h + idx) = v;
}
__global__ void k_colstats4() {
    int grp = blockIdx.x >> 8;
    int blk = blockIdx.x & 255;
    const float* x;
    int nrows;
    switch (grp) {
        case 0: x = g_xb; nrows = NAB; break;
        case 1: x = g_xb + NAB * FDIM; nrows = NAG; break;
        case 2: x = g_h; nrows = NAB; break;
        default: x = g_h + NAB * FDIM; nrows = NAG; break;
    }
    int col = threadIdx.x;
    float s = 0.f, q = 0.f;
    for (int r = blk; r < nrows; r += 256) {
        float v = x[r * FDIM + col];
        s += v;
        q += v * v;
    }
    atomicAdd(&g_csum[grp][col], s);
    atomicAdd(&g_csq[grp][col], q);
}

// ---------------- GAT ----------------
__global__ void k_dots(const float* __restrict__ a_s, const float* __restrict__ a_d) {
    int w = (blockIdx.x * blockDim.x + threadIdx.x) >> 5;
    int lane = threadIdx.x & 31;
    if (w >= NTOT) return;
    const float4* hp = (const float4*)(g_tmp + (long)w * FDIM);
    const float4* ap = (const float4*)a_s;
    const float4* dp = (const float4*)a_d;
    float s = 0.f, d = 0.f;
#pragma unroll
    for (int c = 0; c < 2; c++) {
        float4 hv = hp[lane + c * 32];
        float4 av = ap[lane + c * 32];
        float4 dv = dp[lane + c * 32];
        s += hv.x * av.x + hv.y * av.y + hv.z * av.z + hv.w * av.w;
        d += hv.x * dv.x + hv.y * dv.y + hv.z * dv.z + hv.w * dv.w;
    }
#pragma unroll
    for (int o = 16; o; o >>= 1) {
        s += __shfl_xor_sync(0xFFFFFFFFu, s, o);
        d += __shfl_xor_sync(0xFFFFFFFFu, d, o);
    }
    if (lane == 0) {
        g_es[w] = s;
        g_ed[w] = d;
    }
}
__global__ void k_gat_pull(int accwhich, const float* __restrict__ b, int dorelu) {
    int w = (blockIdx.x * blockDim.x + threadIdx.x) >> 5;
    int lane = threadIdx.x & 31;
    if (w >= NTOT) return;
    int rb = 2 * NTOT;
    int r0 = g_rowg[rb + w], r1 = g_rowg[rb + w + 1];
    float edd = g_ed[w];
    float eself = lrelu(g_es[w] + edd);
    float m = eself;
    for (int j = r0 + lane; j < r1; j += 32) {
        m = fmaxf(m, lrelu(g_es[g_srt[j]] + edd));
    }
#pragma unroll
    for (int o = 16; o; o >>= 1) m = fmaxf(m, __shfl_xor_sync(0xFFFFFFFFu, m, o));
    float exs = __expf(eself - m);
    float ssum = exs;
    const float4* hp = (const float4*)(g_tmp + (long)w * FDIM);
    float4 a0 = hp[lane];
    float4 a1 = hp[lane + 32];
    a0.x *= exs; a0.y *= exs; a0.z *= exs; a0.w *= exs;
    a1.x *= exs; a1.y *= exs; a1.z *= exs; a1.w *= exs;
    for (int j = r0; j < r1; j++) {
        int s = g_srt[j];
        float ex = __expf(lrelu(g_es[s] + edd) - m);
        ssum += ex;
        const float4* sp = (const float4*)(g_tmp + (long)s * FDIM);
        float4 v0 = sp[lane];
        float4 v1 = sp[lane + 32];
        a0.x += v0.x * ex; a0.y += v0.y * ex; a0.z += v0.z * ex; a0.w += v0.w * ex;
        a1.x += v1.x * ex; a1.y += v1.y * ex; a1.z += v1.z * ex; a1.w += v1.w * ex;
    }
    float inv = 1.0f / ssum;
    float4 b0 = *((const float4*)b + lane);
    float4 b1 = *((const float4*)b + lane + 32);
    a0.x = a0.x * inv + b0.x; a0.y = a0.y * inv + b0.y;
    a0.z = a0.z * inv + b0.z; a0.w = a0.w * inv + b0.w;
    a1.x = a1.x * inv + b1.x; a1.y = a1.y * inv + b1.y;
    a1.z = a1.z * inv + b1.z; a1.w = a1.w * inv + b1.w;
    if (dorelu) {
        a0.x = fmaxf(a0.x, 0.f); a0.y = fmaxf(a0.y, 0.f);
        a0.z = fmaxf(a0.z, 0.f); a0.w = fmaxf(a0.w, 0.f);
        a1.x = fmaxf(a1.x, 0.f); a1.y = fmaxf(a1.y, 0.f);
        a1.z = fmaxf(a1.z, 0.f); a1.w = fmaxf(a1.w, 0.f);
    }
    float4* op = (float4*)(BUF(accwhich) + (long)w * FDIM);
    op[lane] = a0;
    op[lane + 32] = a1;
}

// ---------------- final heads (grid = NTOT) ----------------
__global__ void k_head2(const float* __restrict__ g2, const float* __restrict__ be2,
                        const float* __restrict__ W_fc, const float* __restrict__ b_fc,
                        const float* __restrict__ ag_g2, const float* __restrict__ ag_be2,
                        const float* __restrict__ W_agfc, const float* __restrict__ b_agfc,
                        float* __restrict__ out) {
    __shared__ float red[8];
    int row = blockIdx.x;
    int t = threadIdx.x;
    int lane = t & 31, wid = t >> 5;
    const float *xpart, *hpart, *g, *be, *W, *b;
    int slot_x, slot_h, lrow;
    if (row < NAB) {
        lrow = row;
        xpart = g_xb; hpart = g_h;
        slot_x = 0; slot_h = 2;
        g = g2; be = be2; W = W_fc; b = b_fc;
    } else {
        lrow = row - NAB;
        xpart = g_xb + NAB * FDIM; hpart = g_h + NAB * FDIM;
        slot_x = 1; slot_h = 3;
        g = ag_g2; be = ag_be2; W = W_agfc; b = b_agfc;
    }
    float n = (float)NAB;  // NAB == NAG
    float mu1 = g_csum[slot_x][t] / n;
    float var1 = g_csq[slot_x][t] / n - mu1 * mu1;
    float v1 = (xpart[lrow * FDIM + t] - mu1) * rsqrtf(var1 + EPSV) * g[t] + be[t];
    v1 = v1 > 0.f ? v1 : 0.f;
    float mu2 = g_csum[slot_h][t] / n;
    float var2 = g_csq[slot_h][t] / n - mu2 * mu2;
    float v2 = (hpart[lrow * FDIM + t] - mu2) * rsqrtf(var2 + EPSV) * g[FDIM + t] + be[FDIM + t];
    v2 = v2 > 0.f ? v2 : 0.f;
    float p = v1 * W[t] + v2 * W[FDIM + t];
#pragma unroll
    for (int o = 16; o; o >>= 1) p += __shfl_xor_sync(0xFFFFFFFFu, p, o);
    if (lane == 0) red[wid] = p;
    __syncthreads();
    if (t == 0) {
        float acc = red[0];
#pragma unroll
        for (int i = 1; i < 8; i++) acc += red[i];
        out[row] = acc + b[0];
    }
}

// ---------------- host orchestration (launches ONLY) ----------------
static void run_gat(int inwhich, const float* W, const float* a_s, const float* a_d,
                    const float* b, int accwhich, int dorelu) {
    dim3 gg(2, (NTOT + 127) / 128);
    k_gemm<<<gg, 256>>>(nullptr, inwhich, W, NTOT);
    k_dots<<<(NTOT + 7) / 8, 256>>>(a_s, a_d);
    k_gat_pull<<<(NTOT + 7) / 8, 256>>>(accwhich, b, dorelu);
}

extern "C" void kernel_launch(void* const* d_in, const int* in_sizes, int n_in, void* d_out,
                              int out_size) {
    const float* x_ab = (const float*)d_in[0];
    const float* x_ag = (const float*)d_in[1];
    const float* W_gcn = (const float*)d_in[2];
    const float* b_gcn = (const float*)d_in[3];
    const float* g1 = (const float*)d_in[4];
    const float* be1 = (const float*)d_in[5];
    const float* W_aggcn = (const float*)d_in[6];
    const float* b_aggcn = (const float*)d_in[7];
    const float* ag_g1 = (const float*)d_in[8];
    const float* ag_be1 = (const float*)d_in[9];
    const float* W_gat = (const float*)d_in[10];
    const float* a_src = (const float*)d_in[11];
    const float* a_dst = (const float*)d_in[12];
    const float* b_gat = (const float*)d_in[13];
    const float* W_gat2 = (const float*)d_in[14];
    const float* a_src2 = (const float*)d_in[15];
    const float* a_dst2 = (const float*)d_in[16];
    const float* b_gat2 = (const float*)d_in[17];
    const float* ag_g2 = (const float*)d_in[18];
    const float* ag_be2 = (const float*)d_in[19];
    const float* W_agfc = (const float*)d_in[20];
    const float* b_agfc = (const float*)d_in[21];
    const float* g2 = (const float*)d_in[22];
    const float* be2 = (const float*)d_in[23];
    const float* W_fc = (const float*)d_in[24];
    const float* b_fc = (const float*)d_in[25];
    const int* e_ab = (const int*)d_in[26];
    const int* e_ag = (const int*)d_in[27];
    const int* e_d = (const int*)d_in[28];
    float* out = (float*)d_out;

    // batched CSR build (all 3 graphs, global prefix)
    k_zero_csr<<<(CSRN + 255) / 256, 256>>>();
    k_hist_all<<<(ETOT + 255) / 256, 256>>>(e_ab + EAB, e_ag + EAG, e_d + ED);
    k_scan1<<<SCAN_BLOCKS, 1024>>>();
    k_scan2<<<1, 128>>>();
    k_scan3<<<SCAN_BLOCKS, 1024>>>();
    k_fill_all<<<(ETOT + 255) / 256, 256>>>(e_ab, e_ag, e_d);

    // both GCNs fused: dual GEMM -> merged pull -> merged stats -> merged bn_relu
    {
        dim3 gg(2, (NAB + 127) / 128, 2);
        k_gemm2<<<gg, 256>>>(x_ab, W_gcn, x_ag, W_aggcn);
        k_gcn_pull2<<<(NTOT + 7) / 8, 256>>>(b_gcn, b_aggcn);
        k_zero_stats<<<2, 256>>>();
        k_colstats2<<<512, 256>>>();
        k_bn_relu2<<<(NTOT * 64 + 255) / 256, 256>>>(g1, be1, ag_g1, ag_be1);
    }

    // GAT layer 1: g_h(0) -> g_xa(1), relu
    run_gat(0, W_gat, a_src, a_dst, b_gat, 1, 1);
    // GAT layer 2: g_xa(1) -> g_xb(2), no relu
    run_gat(1, W_gat2, a_src2, a_dst2, b_gat2, 2, 0);

    // head stats + heads
    k_zero_stats<<<4, 256>>>();
    k_colstats4<<<1024, 256>>>();
    k_head2<<<NTOT, 256>>>(g2, be2, W_fc, b_fc, ag_g2, ag_be2, W_agfc, b_agfc, out);
}